// round 4
// baseline (speedup 1.0000x reference)
#include <cuda_runtime.h>
#include <math.h>
#include <stdint.h>

#define BATCH 65536
#define D0 784
#define D1 512
#define D2 256
#define D3 10
#define KP1 800            // 784 padded to 25*32
#define KP2 512
#define K_DESC 32768
#define R_ASC (BATCH - 1 - K_DESC)   // 32767

// Does this compilation pass support tcgen05 (arch-specific sm_103a/sm_100a)?
#if defined(__CUDA_ARCH__) && (defined(__CUDA_ARCH_FEAT_SM103_ALL) || \
                               defined(__CUDA_ARCH_FEAT_SM100_ALL) || \
                               defined(__CUDA_ARCH_SPECIFIC__)     || \
                               defined(__CUDA_ARCH_FAMILY_SPECIFIC__))
#define USE_TC 1
#else
#define USE_TC 0
#endif

// tf32 SS MMA idesc: dtype=F32(1<<4), atype=TF32(2<<7), btype=TF32(2<<10),
// N=128 -> (128>>3)<<17, M=128 -> (128>>4)<<24
#define IDESC_TF32 ((1u<<4)|(2u<<7)|(2u<<10)|((128u>>3)<<17)|((128u>>4)<<24))

// SW128 smem descriptor base (layout=2, version=1, SBO=64, LBO=1)
#define DESC_BASE ((2ull<<61)|(1ull<<46)|(64ull<<32)|(1ull<<16))

// ---------------- scratch -----------------------------------------------------
__device__ float g_h1[(size_t)BATCH * D1];
__device__ float g_h2[(size_t)BATCH * D2];
__device__ float g_h3[(size_t)BATCH * D3];
__device__ float g_h4[(size_t)BATCH * D3];
__device__ float g_norm[BATCH];
__device__ float g_mask1[BATCH];
__device__ float g_mask2[BATCH];
__device__ float g_mask3[BATCH];
__device__ float g_part[4 * BATCH];
__device__ float g_w1hT[(size_t)D1 * KP1];
__device__ float g_w1lT[(size_t)D1 * KP1];
__device__ float g_w2hT[(size_t)D2 * KP2];
__device__ float g_w2lT[(size_t)D2 * KP2];
__device__ unsigned g_hist[4][65536];
__device__ float g_thr[1];

// ---------------- helpers (safe on all targets) -------------------------------
__device__ __forceinline__ uint32_t smem_u32(const void* p) {
    uint32_t a;
    asm("{ .reg .u64 t; cvta.to.shared.u64 t, %1; cvt.u32.u64 %0, t; }" : "=r"(a) : "l"(p));
    return a;
}
__device__ __forceinline__ float trunc_tf32(float v) {
    return __uint_as_float(__float_as_uint(v) & 0xffffe000u);
}

#if USE_TC
__device__ __forceinline__ void sts128(uint32_t addr, float4 v) {
    asm volatile("st.shared.v4.f32 [%0], {%1,%2,%3,%4};"
                 :: "r"(addr), "f"(v.x), "f"(v.y), "f"(v.z), "f"(v.w) : "memory");
}
__device__ __forceinline__ void mbar_init(uint32_t addr) {
    asm volatile("mbarrier.init.shared.b64 [%0], 1;" :: "r"(addr) : "memory");
}
__device__ __forceinline__ void mbar_inval(uint32_t addr) {
    asm volatile("mbarrier.inval.shared.b64 [%0];" :: "r"(addr) : "memory");
}
__device__ __forceinline__ void mbar_wait(uint32_t addr, int parity) {
    asm volatile(
        "{\n\t.reg .pred P;\n"
        "WL_%=:\n\t"
        "mbarrier.try_wait.parity.acquire.cta.shared::cta.b64 P, [%0], %1, 0x989680;\n\t"
        "@P bra.uni WD_%=;\n\t"
        "bra.uni WL_%=;\n"
        "WD_%=:\n\t}"
        :: "r"(addr), "r"(parity) : "memory");
}
__device__ __forceinline__ void tmem_alloc(uint32_t smem_dst, uint32_t ncols) {
    asm volatile("tcgen05.alloc.cta_group::1.sync.aligned.shared::cta.b32 [%0], %1;"
                 :: "r"(smem_dst), "r"(ncols) : "memory");
}
__device__ __forceinline__ void tmem_dealloc(uint32_t tmem, uint32_t ncols) {
    asm volatile("tcgen05.relinquish_alloc_permit.cta_group::1.sync.aligned;");
    asm volatile("tcgen05.dealloc.cta_group::1.sync.aligned.b32 %0, %1;" :: "r"(tmem), "r"(ncols));
}
__device__ __forceinline__ void mma_tf32(uint32_t d, uint64_t ad, uint64_t bd, bool accum) {
    uint32_t en = accum ? 1u : 0u;
    asm volatile(
        "{\n\t.reg .pred p;\n\t"
        "setp.ne.u32 p, %4, 0;\n\t"
        "tcgen05.mma.cta_group::1.kind::tf32 [%0], %1, %2, %3, {%5,%5,%5,%5}, p;\n\t}"
        :: "r"(d), "l"(ad), "l"(bd), "r"(IDESC_TF32), "r"(en), "r"(0u) : "memory");
}
__device__ __forceinline__ void mma_commit(uint32_t mbar) {
    asm volatile("tcgen05.commit.cta_group::1.mbarrier::arrive::one.shared::cluster.b64 [%0];"
                 :: "r"(mbar) : "memory");
}
#define LDTM_X32(r, addr) \
    asm volatile( \
        "tcgen05.ld.sync.aligned.32x32b.x32.b32 " \
        "{%0, %1, %2, %3, %4, %5, %6, %7, " \
        " %8, %9, %10, %11, %12, %13, %14, %15, " \
        " %16, %17, %18, %19, %20, %21, %22, %23, " \
        " %24, %25, %26, %27, %28, %29, %30, %31}, [%32];" \
        : "=r"((r)[0]),  "=r"((r)[1]),  "=r"((r)[2]),  "=r"((r)[3]), \
          "=r"((r)[4]),  "=r"((r)[5]),  "=r"((r)[6]),  "=r"((r)[7]), \
          "=r"((r)[8]),  "=r"((r)[9]),  "=r"((r)[10]), "=r"((r)[11]), \
          "=r"((r)[12]), "=r"((r)[13]), "=r"((r)[14]), "=r"((r)[15]), \
          "=r"((r)[16]), "=r"((r)[17]), "=r"((r)[18]), "=r"((r)[19]), \
          "=r"((r)[20]), "=r"((r)[21]), "=r"((r)[22]), "=r"((r)[23]), \
          "=r"((r)[24]), "=r"((r)[25]), "=r"((r)[26]), "=r"((r)[27]), \
          "=r"((r)[28]), "=r"((r)[29]), "=r"((r)[30]), "=r"((r)[31]) \
        : "r"(addr))

__device__ __forceinline__ uint64_t mkdesc(uint32_t addr) {
    return DESC_BASE | ((uint64_t)(addr >> 4) & 0x3FFFull);
}
#endif  // USE_TC

// ---------------- weight transpose + tf32 split (one-time per launch) ---------
__global__ void prep_split_T(const float* __restrict__ W, float* __restrict__ hiT,
                             float* __restrict__ loT, int K, int N, int KP) {
    int idx = blockIdx.x * blockDim.x + threadIdx.x;
    if (idx >= N * KP) return;
    int n = idx / KP, k = idx % KP;
    float v = (k < K) ? W[(size_t)k * N + n] : 0.0f;
    float h = trunc_tf32(v);
    hiT[idx] = h;
    loT[idx] = v - h;
}

__global__ void zero_hists_kernel(unsigned* h) {
    int i = blockIdx.x * blockDim.x + threadIdx.x;
    if (i < 4 * 65536) h[i] = 0u;
}

// ---------------- GEMM: C = relu(A @ B^T + bias), fused sumsq partials --------
// A [M,K] fp32 (optionally row-masked), B^T pre-split BhT/BlT [N, KP] K-major.
// Tile 128x128, chunk 32 of K, 2-stage mbarrier pipe on the tcgen05 path.
__global__ __launch_bounds__(128)
void gemm_tc(const float* __restrict__ A, const float* __restrict__ BhT,
             const float* __restrict__ BlT, const float* __restrict__ bias,
             const float* __restrict__ mask, float* __restrict__ C,
             float* __restrict__ part, int K, int KP, int N, int nchunks) {
    extern __shared__ char smem[];
    const int tid = threadIdx.x;
    const int m0 = blockIdx.y * 128;
    const int n0 = blockIdx.x * 128;

#if USE_TC
    const uint32_t sb = smem_u32(smem);
    if (tid == 0) { mbar_init(sb + 8); mbar_init(sb + 16); }
    if (tid < 32) tmem_alloc(sb, 128);
    __syncthreads();
    uint32_t tmem;
    asm volatile("ld.shared.b32 %0, [%1];" : "=r"(tmem) : "r"(sb));

    // load mapping: 8 quads/thread; row = q*16 + (tid>>3), quad = tid&7 (16B)
    const int lrow0 = tid >> 3;
    const int quad = tid & 7;
    float rmul[8];
#pragma unroll
    for (int q = 0; q < 8; q++)
        rmul[q] = mask ? mask[m0 + q * 16 + lrow0] : 1.0f;

    int ph0 = 0, ph1 = 0;
#pragma unroll 1
    for (int t = 0; t < nchunks; t++) {
        const int s = t & 1;
        if (t >= 2) {
            if (s == 0) { mbar_wait(sb + 8, ph0);  ph0 ^= 1; }
            else        { mbar_wait(sb + 16, ph1); ph1 ^= 1; }
        }
        const uint32_t stb = sb + 1024 + s * 65536;
        const int k0 = t * 32;

        // A tile: LDG fp32, split hi/lo, STS swizzled
#pragma unroll
        for (int q = 0; q < 8; q++) {
            const int row = q * 16 + lrow0;
            const int k = k0 + quad * 4;
            float4 v = make_float4(0.f, 0.f, 0.f, 0.f);
            if (k < K) v = *reinterpret_cast<const float4*>(A + (size_t)(m0 + row) * K + k);
            const float ml = rmul[q];
            v.x *= ml; v.y *= ml; v.z *= ml; v.w *= ml;
            float4 h, l;
            h.x = trunc_tf32(v.x); l.x = v.x - h.x;
            h.y = trunc_tf32(v.y); l.y = v.y - h.y;
            h.z = trunc_tf32(v.z); l.z = v.z - h.z;
            h.w = trunc_tf32(v.w); l.w = v.w - h.w;
            uint32_t boff = row * 128 + quad * 16;
            uint32_t swo = boff ^ ((boff >> 3) & 0x70);
            sts128(stb + swo, h);
            sts128(stb + 16384 + swo, l);
        }
        // B tiles (pre-split)
#pragma unroll
        for (int q = 0; q < 8; q++) {
            const int row = q * 16 + lrow0;
            const int k = k0 + quad * 4;
            float4 h = *reinterpret_cast<const float4*>(BhT + (size_t)(n0 + row) * KP + k);
            float4 l = *reinterpret_cast<const float4*>(BlT + (size_t)(n0 + row) * KP + k);
            uint32_t boff = row * 128 + quad * 16;
            uint32_t swo = boff ^ ((boff >> 3) & 0x70);
            sts128(stb + 32768 + swo, h);
            sts128(stb + 49152 + swo, l);
        }
        asm volatile("fence.proxy.async.shared::cta;" ::: "memory");
        __syncthreads();

        if (tid == 0) {
            const uint64_t ah = mkdesc(stb);
            const uint64_t al = mkdesc(stb + 16384);
            const uint64_t bh = mkdesc(stb + 32768);
            const uint64_t bl = mkdesc(stb + 49152);
#pragma unroll
            for (int ks = 0; ks < 4; ks++) {
                mma_tf32(tmem, ah + ks * 2, bh + ks * 2, !(t == 0 && ks == 0));
                mma_tf32(tmem, ah + ks * 2, bl + ks * 2, true);
                mma_tf32(tmem, al + ks * 2, bh + ks * 2, true);
            }
            mma_commit(sb + 8 + 8 * s);
        }
    }
    // final drain (in-order completion: last chunk's commit implies all done)
    {
        const int s = (nchunks - 1) & 1;
        if (s == 0) mbar_wait(sb + 8, ph0);
        else        mbar_wait(sb + 16, ph1);
    }
    asm volatile("tcgen05.fence::after_thread_sync;" ::: "memory");

    // epilogue: bias + relu + store + fused sumsq partial
    const int wid = tid >> 5, lane = tid & 31;
    const int m = m0 + wid * 32 + lane;
    float sumsq = 0.0f;
#pragma unroll
    for (int cc = 0; cc < 4; cc++) {
        uint32_t r[32];
        LDTM_X32(r, tmem + cc * 32);
        asm volatile("tcgen05.wait::ld.sync.aligned;" ::: "memory");
        float vals[32];
#pragma unroll
        for (int j = 0; j < 32; j++) {
            float v = __uint_as_float(r[j]) + bias[n0 + cc * 32 + j];
            v = fmaxf(v, 0.0f);
            sumsq += v * v;
            vals[j] = v;
        }
#pragma unroll
        for (int j4 = 0; j4 < 8; j4++) {
            float4 o = make_float4(vals[j4 * 4], vals[j4 * 4 + 1],
                                   vals[j4 * 4 + 2], vals[j4 * 4 + 3]);
            *reinterpret_cast<float4*>(C + (size_t)m * N + n0 + cc * 32 + j4 * 4) = o;
        }
    }
    part[(size_t)blockIdx.x * BATCH + m] = sumsq;

    __syncthreads();
    if (tid == 0) { mbar_inval(sb + 8); mbar_inval(sb + 16); }
    __syncthreads();
    if (tid < 32) tmem_dealloc(tmem, 128);

#else  // ------- generic-target fallback (correct, FFMA, only used if the ----
       // ------- sm_103a cubin pass is absent at runtime) ---------------------
    float* Asm = reinterpret_cast<float*>(smem);            // 128 x 32 tile
    float* Bsm = Asm + 128 * 32;                            // 32 x 32 tile
    const int row = tid;
    const float ml = mask ? mask[m0 + row] : 1.0f;
    float sumsq = 0.0f;
    for (int cc = 0; cc < 4; cc++) {
        float acc[32];
#pragma unroll
        for (int j = 0; j < 32; j++) acc[j] = 0.0f;
        for (int k0 = 0; k0 < K; k0 += 32) {
            // load A tile 128x32 (each thread loads its row's 32 k-values)
#pragma unroll
            for (int kk = 0; kk < 32; kk++) {
                int k = k0 + kk;
                Asm[row * 32 + kk] = (k < K) ?
                    A[(size_t)(m0 + row) * K + k] * ml : 0.0f;
            }
            // load B tile 32(n) x 32(k): thread tid -> n = tid>>2 (8 n per 32thr?) use loop
            for (int idx = tid; idx < 32 * 32; idx += 128) {
                int nn = idx >> 5, kk = idx & 31;
                int k = k0 + kk;
                float bv = BhT[(size_t)(n0 + cc * 32 + nn) * KP + k] +
                           BlT[(size_t)(n0 + cc * 32 + nn) * KP + k];
                Bsm[nn * 32 + kk] = bv;
            }
            __syncthreads();
#pragma unroll 4
            for (int kk = 0; kk < 32; kk++) {
                float a = Asm[row * 32 + kk];
#pragma unroll
                for (int j = 0; j < 32; j++) acc[j] += a * Bsm[j * 32 + kk];
            }
            __syncthreads();
        }
#pragma unroll
        for (int j = 0; j < 32; j++) {
            float v = fmaxf(acc[j] + bias[n0 + cc * 32 + j], 0.0f);
            sumsq += v * v;
            C[(size_t)(m0 + row) * N + n0 + cc * 32 + j] = v;
        }
    }
    part[(size_t)blockIdx.x * BATCH + (m0 + row)] = sumsq;
#endif
}

// ---------------- combine partials -> norm + hist16 ---------------------------
__global__ void combine_kernel(const float* __restrict__ part, int nb,
                               float* __restrict__ norms, unsigned* __restrict__ hist) {
    int i = blockIdx.x * blockDim.x + threadIdx.x;
    if (i >= BATCH) return;
    float s = 0.0f;
    for (int b = 0; b < nb; b++) s += part[(size_t)b * BATCH + i];
    float n = sqrtf(s);
    norms[i] = n;
    atomicAdd(&hist[__float_as_uint(n) >> 16], 1u);
}

// ---------------- select threshold: hist16 prescan + 2x 8-bit refine ----------
__global__ void select_thr_kernel(const float* __restrict__ norms,
                                  const unsigned* __restrict__ hist,
                                  float* __restrict__ thr) {
    __shared__ unsigned psum[1024];
    __shared__ unsigned h8[256];
    __shared__ unsigned s_pref, s_rank;
    const int tid = threadIdx.x;

    unsigned s = 0;
#pragma unroll 8
    for (int j = 0; j < 64; j++) s += hist[tid * 64 + j];
    psum[tid] = s;
    __syncthreads();
    if (tid == 0) {
        unsigned cum = 0;
        int slice = 0;
        for (slice = 0; slice < 1024; slice++) {
            if (cum + psum[slice] > (unsigned)R_ASC) break;
            cum += psum[slice];
        }
        unsigned b = slice * 64;
        for (;; b++) {
            if (cum + hist[b] > (unsigned)R_ASC) break;
            cum += hist[b];
        }
        s_pref = b;                      // 16-bit prefix
        s_rank = (unsigned)R_ASC - cum;
    }
    __syncthreads();

    if (tid < 256) h8[tid] = 0u;
    __syncthreads();
    unsigned pref16 = s_pref;
    for (int i = tid; i < BATCH; i += 1024) {
        unsigned u = __float_as_uint(norms[i]);
        if ((u >> 16) == pref16) atomicAdd(&h8[(u >> 8) & 0xffu], 1u);
    }
    __syncthreads();
    if (tid == 0) {
        unsigned cum = 0, b = 0, r = s_rank;
        for (b = 0; b < 256; b++) {
            if (cum + h8[b] > r) break;
            cum += h8[b];
        }
        s_pref = (pref16 << 8) | b;
        s_rank = r - cum;
    }
    __syncthreads();

    if (tid < 256) h8[tid] = 0u;
    __syncthreads();
    unsigned pref24 = s_pref;
    for (int i = tid; i < BATCH; i += 1024) {
        unsigned u = __float_as_uint(norms[i]);
        if ((u >> 8) == pref24) atomicAdd(&h8[u & 0xffu], 1u);
    }
    __syncthreads();
    if (tid == 0) {
        unsigned cum = 0, b = 0, r = s_rank;
        for (b = 0; b < 256; b++) {
            if (cum + h8[b] > r) break;
            cum += h8[b];
        }
        thr[0] = __uint_as_float((pref24 << 8) | b);
    }
}

__global__ void write_mask_kernel(const float* __restrict__ norms,
                                  const float* __restrict__ thr,
                                  float* __restrict__ ma, float* __restrict__ mb) {
    int i = blockIdx.x * blockDim.x + threadIdx.x;
    if (i >= BATCH) return;
    float mv = (norms[i] > thr[0]) ? 1.0f : 0.0f;
    ma[i] = mv;
    mb[i] = mv;
}

// ---------------- layer 3: [B,256] -> [B,10], relu, fused norm+hist ----------
__global__ __launch_bounds__(256)
void layer3_kernel(const float* __restrict__ H2, const float* __restrict__ mask2,
                   const float* __restrict__ W3, const float* __restrict__ b3,
                   float* __restrict__ H3, float* __restrict__ norms,
                   unsigned* __restrict__ hist) {
    __shared__ float Ws[D2 * D3];
    __shared__ float bs[D3];
    for (int i = threadIdx.x; i < D2 * D3; i += blockDim.x) Ws[i] = W3[i];
    if (threadIdx.x < D3) bs[threadIdx.x] = b3[threadIdx.x];
    __syncthreads();

    int row = (blockIdx.x * blockDim.x + threadIdx.x) >> 5;
    int lane = threadIdx.x & 31;
    if (row >= BATCH) return;
    float m = mask2[row];
    float p[D3];
#pragma unroll
    for (int n = 0; n < D3; n++) p[n] = 0.0f;
#pragma unroll
    for (int t = 0; t < D2 / 32; t++) {
        int k = lane + 32 * t;
        float a = H2[(size_t)row * D2 + k] * m;
        const float* wrow = &Ws[k * D3];
#pragma unroll
        for (int n = 0; n < D3; n++) p[n] += a * wrow[n];
    }
#pragma unroll
    for (int o = 16; o; o >>= 1)
#pragma unroll
        for (int n = 0; n < D3; n++) p[n] += __shfl_down_sync(0xffffffffu, p[n], o);

    if (lane == 0) {
        float ssum = 0.0f;
#pragma unroll
        for (int n = 0; n < D3; n++) {
            float v = fmaxf(p[n] + bs[n], 0.0f);
            H3[(size_t)row * D3 + n] = v;
            ssum += v * v;
        }
        float nr = sqrtf(ssum);
        norms[row] = nr;
        atomicAdd(&hist[__float_as_uint(nr) >> 16], 1u);
    }
}

// ---------------- layer 4 + fused norm+hist ----------------------------------
__global__ __launch_bounds__(256)
void layer4_kernel(const float* __restrict__ H3, const float* __restrict__ mask3,
                   const float* __restrict__ W4, const float* __restrict__ b4,
                   float* __restrict__ H4, float* __restrict__ norms,
                   unsigned* __restrict__ hist) {
    __shared__ float Ws[D3 * D3];
    __shared__ float bs[D3];
    if (threadIdx.x < D3 * D3) Ws[threadIdx.x] = W4[threadIdx.x];
    if (threadIdx.x < D3) bs[threadIdx.x] = b4[threadIdx.x];
    __syncthreads();

    int row = blockIdx.x * blockDim.x + threadIdx.x;
    if (row >= BATCH) return;
    float m = mask3[row];
    float a[D3];
#pragma unroll
    for (int k = 0; k < D3; k++) a[k] = H3[(size_t)row * D3 + k] * m;
    float ssum = 0.0f;
#pragma unroll
    for (int n = 0; n < D3; n++) {
        float v = bs[n];
#pragma unroll
        for (int k = 0; k < D3; k++) v += a[k] * Ws[k * D3 + n];
        H4[(size_t)row * D3 + n] = v;
        ssum += v * v;
    }
    float nr = sqrtf(ssum);
    norms[row] = nr;
    atomicAdd(&hist[__float_as_uint(nr) >> 16], 1u);
}

// ---------------- softmax over masked h4 -------------------------------------
__global__ __launch_bounds__(256)
void softmax_kernel(const float* __restrict__ H4, const float* __restrict__ norms,
                    const float* __restrict__ thr, float* __restrict__ out,
                    float* __restrict__ out_mask) {
    int row = blockIdx.x * blockDim.x + threadIdx.x;
    if (row >= BATCH) return;
    float m = (norms[row] > thr[0]) ? 1.0f : 0.0f;
    out_mask[row] = m;
    float v[D3];
    float mx = -1e30f;
#pragma unroll
    for (int n = 0; n < D3; n++) {
        v[n] = H4[(size_t)row * D3 + n] * m;
        mx = fmaxf(mx, v[n]);
    }
    float s = 0.0f;
#pragma unroll
    for (int n = 0; n < D3; n++) { v[n] = expf(v[n] - mx); s += v[n]; }
    float inv = 1.0f / s;
#pragma unroll
    for (int n = 0; n < D3; n++) out[(size_t)row * D3 + n] = v[n] * inv;
}

// ---------------- launch -----------------------------------------------------
#define GEMM_SMEM (1024 + 2 * 65536)

extern "C" void kernel_launch(void* const* d_in, const int* in_sizes, int n_in,
                              void* d_out, int out_size) {
    const float* x  = (const float*)d_in[0];
    const float* W1 = (const float*)d_in[1];
    const float* b1 = (const float*)d_in[2];
    const float* W2 = (const float*)d_in[3];
    const float* b2 = (const float*)d_in[4];
    const float* W3 = (const float*)d_in[5];
    const float* b3 = (const float*)d_in[6];
    const float* W4 = (const float*)d_in[7];
    const float* b4 = (const float*)d_in[8];
    float* out = (float*)d_out;

    float *h1, *h2, *h3, *h4, *nrm, *m1, *m2, *m3, *part, *thr;
    float *w1h, *w1l, *w2h, *w2l;
    unsigned* hist;
    cudaGetSymbolAddress((void**)&h1, g_h1);
    cudaGetSymbolAddress((void**)&h2, g_h2);
    cudaGetSymbolAddress((void**)&h3, g_h3);
    cudaGetSymbolAddress((void**)&h4, g_h4);
    cudaGetSymbolAddress((void**)&nrm, g_norm);
    cudaGetSymbolAddress((void**)&m1, g_mask1);
    cudaGetSymbolAddress((void**)&m2, g_mask2);
    cudaGetSymbolAddress((void**)&m3, g_mask3);
    cudaGetSymbolAddress((void**)&part, g_part);
    cudaGetSymbolAddress((void**)&thr, g_thr);
    cudaGetSymbolAddress((void**)&w1h, g_w1hT);
    cudaGetSymbolAddress((void**)&w1l, g_w1lT);
    cudaGetSymbolAddress((void**)&w2h, g_w2hT);
    cudaGetSymbolAddress((void**)&w2l, g_w2lT);
    cudaGetSymbolAddress((void**)&hist, g_hist);

    cudaFuncSetAttribute(gemm_tc, cudaFuncAttributeMaxDynamicSharedMemorySize, GEMM_SMEM);

    float* out_m1 = out + (size_t)BATCH * D3;
    float* out_m2 = out_m1 + BATCH;
    float* out_m3 = out_m2 + BATCH;
    float* out_m4 = out_m3 + BATCH;

    unsigned* hist0 = hist;
    unsigned* hist1 = hist + 65536;
    unsigned* hist2 = hist + 2 * 65536;
    unsigned* hist3 = hist + 3 * 65536;

    zero_hists_kernel<<<(4 * 65536) / 256, 256>>>(hist);
    prep_split_T<<<(D1 * KP1 + 255) / 256, 256>>>(W1, w1h, w1l, D0, D1, KP1);
    prep_split_T<<<(D2 * KP2 + 255) / 256, 256>>>(W2, w2h, w2l, D1, D2, KP2);

    // Layer 1: [B,784] -> [B,512]
    {
        dim3 grid(D1 / 128, BATCH / 128);
        gemm_tc<<<grid, 128, GEMM_SMEM>>>(x, w1h, w1l, b1, nullptr, h1, part,
                                          D0, KP1, D1, KP1 / 32);
    }
    combine_kernel<<<BATCH / 256, 256>>>(part, 4, nrm, hist0);
    select_thr_kernel<<<1, 1024>>>(nrm, hist0, thr);
    write_mask_kernel<<<BATCH / 256, 256>>>(nrm, thr, m1, out_m1);

    // Layer 2: [B,512] -> [B,256], mask1 on input rows
    {
        dim3 grid(D2 / 128, BATCH / 128);
        gemm_tc<<<grid, 128, GEMM_SMEM>>>(h1, w2h, w2l, b2, m1, h2, part,
                                          D1, KP2, D2, KP2 / 32);
    }
    combine_kernel<<<BATCH / 256, 256>>>(part, 2, nrm, hist1);
    select_thr_kernel<<<1, 1024>>>(nrm, hist1, thr);
    write_mask_kernel<<<BATCH / 256, 256>>>(nrm, thr, m2, out_m2);

    // Layer 3
    layer3_kernel<<<(BATCH * 32) / 256, 256>>>(h2, m2, W3, b3, h3, nrm, hist2);
    select_thr_kernel<<<1, 1024>>>(nrm, hist2, thr);
    write_mask_kernel<<<BATCH / 256, 256>>>(nrm, thr, m3, out_m3);

    // Layer 4
    layer4_kernel<<<BATCH / 256, 256>>>(h3, m3, W4, b4, h4, nrm, hist3);
    select_thr_kernel<<<1, 1024>>>(nrm, hist3, thr);

    // Softmax + mask4 write (mask recomputed from norms/thr inside)
    softmax_kernel<<<BATCH / 256, 256>>>(h4, nrm, thr, out, out_m4);
}

// round 5
// speedup vs baseline: 2.7640x; 2.7640x over previous
#include <cuda_runtime.h>
#include <math.h>
#include <stdint.h>

#define BATCH 65536
#define D0 784
#define D1 512
#define D2 256
#define D3 10
#define KP1 800            // 784 padded to 25*32
#define KP2 512
#define K_DESC 32768
#define R_ASC (BATCH - 1 - K_DESC)   // 32767

#define TILE_M 128
#define TILE_N 256
#define CHUNK 32           // K floats per chunk = 128B rows (SW128 atom width)

// Does this compilation pass support tcgen05 (arch-specific sm_103a/sm_100a)?
#if defined(__CUDA_ARCH__) && (defined(__CUDA_ARCH_FEAT_SM103_ALL) || \
                               defined(__CUDA_ARCH_FEAT_SM100_ALL) || \
                               defined(__CUDA_ARCH_SPECIFIC__)     || \
                               defined(__CUDA_ARCH_FAMILY_SPECIFIC__))
#define USE_TC 1
#else
#define USE_TC 0
#endif

// tf32 SS MMA idesc: dtype=F32(1<<4), atype=TF32(2<<7), btype=TF32(2<<10),
// N field = (N/4)<<16, M field = (M/16)<<24  (validated against bf16 example)
#define IDESC_TF32 ((1u<<4)|(2u<<7)|(2u<<10)|((256u/4)<<16)|((128u/16)<<24))

// SW128 smem descriptor base (layout=2, version=1, SBO=64, LBO=1)
#define DESC_BASE ((2ull<<61)|(1ull<<46)|(64ull<<32)|(1ull<<16))

// smem layout
#define SM_BIAS  1024
#define SM_STAGE 2048
#define STAGE_BYTES 98304          // Ah 16K | Al 16K | Bh 32K | Bl 32K
#define OFF_AL 16384
#define OFF_BH 32768
#define OFF_BL 65536
#define GEMM_SMEM (SM_STAGE + 2 * STAGE_BYTES)

// ---------------- scratch -----------------------------------------------------
__device__ float g_xh[(size_t)BATCH * KP1];
__device__ float g_xl[(size_t)BATCH * KP1];
__device__ float g_h1h[(size_t)BATCH * D1];
__device__ float g_h1l[(size_t)BATCH * D1];
__device__ float g_h2[(size_t)BATCH * D2];
__device__ float g_h3[(size_t)BATCH * D3];
__device__ float g_h4[(size_t)BATCH * D3];
__device__ float g_norm[BATCH];
__device__ float g_mask1[BATCH];
__device__ float g_mask2[BATCH];
__device__ float g_mask3[BATCH];
__device__ float g_part[2 * BATCH];
__device__ float g_w1hT[(size_t)D1 * KP1];
__device__ float g_w1lT[(size_t)D1 * KP1];
__device__ float g_w2hT[(size_t)D2 * KP2];
__device__ float g_w2lT[(size_t)D2 * KP2];
__device__ unsigned g_hist[4][65536];
__device__ float g_thr[1];

// ---------------- helpers (safe on all targets) -------------------------------
__device__ __forceinline__ uint32_t smem_u32(const void* p) {
    uint32_t a;
    asm("{ .reg .u64 t; cvta.to.shared.u64 t, %1; cvt.u32.u64 %0, t; }" : "=r"(a) : "l"(p));
    return a;
}
__device__ __forceinline__ float trunc_tf32(float v) {
    return __uint_as_float(__float_as_uint(v) & 0xffffe000u);
}

#if USE_TC
__device__ __forceinline__ void cp16(uint32_t dst, const void* src) {
    asm volatile("cp.async.cg.shared.global [%0], [%1], 16;"
                 :: "r"(dst), "l"(src) : "memory");
}
__device__ __forceinline__ void cp_commit_wait0() {
    asm volatile("cp.async.commit_group;" ::: "memory");
    asm volatile("cp.async.wait_group 0;" ::: "memory");
}
__device__ __forceinline__ void mbar_init(uint32_t addr) {
    asm volatile("mbarrier.init.shared.b64 [%0], 1;" :: "r"(addr) : "memory");
}
__device__ __forceinline__ void mbar_inval(uint32_t addr) {
    asm volatile("mbarrier.inval.shared.b64 [%0];" :: "r"(addr) : "memory");
}
__device__ __forceinline__ void mbar_wait(uint32_t addr, int parity) {
    asm volatile(
        "{\n\t.reg .pred P;\n"
        "WL_%=:\n\t"
        "mbarrier.try_wait.parity.acquire.cta.shared::cta.b64 P, [%0], %1, 0x989680;\n\t"
        "@P bra.uni WD_%=;\n\t"
        "bra.uni WL_%=;\n"
        "WD_%=:\n\t}"
        :: "r"(addr), "r"(parity) : "memory");
}
__device__ __forceinline__ void tmem_alloc(uint32_t smem_dst, uint32_t ncols) {
    asm volatile("tcgen05.alloc.cta_group::1.sync.aligned.shared::cta.b32 [%0], %1;"
                 :: "r"(smem_dst), "r"(ncols) : "memory");
}
__device__ __forceinline__ void tmem_dealloc(uint32_t tmem, uint32_t ncols) {
    asm volatile("tcgen05.relinquish_alloc_permit.cta_group::1.sync.aligned;");
    asm volatile("tcgen05.dealloc.cta_group::1.sync.aligned.b32 %0, %1;" :: "r"(tmem), "r"(ncols));
}
__device__ __forceinline__ void mma_tf32(uint32_t d, uint64_t ad, uint64_t bd, bool accum) {
    uint32_t en = accum ? 1u : 0u;
    asm volatile(
        "{\n\t.reg .pred p;\n\t"
        "setp.ne.u32 p, %4, 0;\n\t"
        "tcgen05.mma.cta_group::1.kind::tf32 [%0], %1, %2, %3, {%5,%5,%5,%5}, p;\n\t}"
        :: "r"(d), "l"(ad), "l"(bd), "r"(IDESC_TF32), "r"(en), "r"(0u) : "memory");
}
__device__ __forceinline__ void mma_commit(uint32_t mbar) {
    asm volatile("tcgen05.commit.cta_group::1.mbarrier::arrive::one.shared::cluster.b64 [%0];"
                 :: "r"(mbar) : "memory");
}
#define LDTM_X32(r, addr) \
    asm volatile( \
        "tcgen05.ld.sync.aligned.32x32b.x32.b32 " \
        "{%0, %1, %2, %3, %4, %5, %6, %7, " \
        " %8, %9, %10, %11, %12, %13, %14, %15, " \
        " %16, %17, %18, %19, %20, %21, %22, %23, " \
        " %24, %25, %26, %27, %28, %29, %30, %31}, [%32];" \
        : "=r"((r)[0]),  "=r"((r)[1]),  "=r"((r)[2]),  "=r"((r)[3]), \
          "=r"((r)[4]),  "=r"((r)[5]),  "=r"((r)[6]),  "=r"((r)[7]), \
          "=r"((r)[8]),  "=r"((r)[9]),  "=r"((r)[10]), "=r"((r)[11]), \
          "=r"((r)[12]), "=r"((r)[13]), "=r"((r)[14]), "=r"((r)[15]), \
          "=r"((r)[16]), "=r"((r)[17]), "=r"((r)[18]), "=r"((r)[19]), \
          "=r"((r)[20]), "=r"((r)[21]), "=r"((r)[22]), "=r"((r)[23]), \
          "=r"((r)[24]), "=r"((r)[25]), "=r"((r)[26]), "=r"((r)[27]), \
          "=r"((r)[28]), "=r"((r)[29]), "=r"((r)[30]), "=r"((r)[31]) \
        : "r"(addr))

__device__ __forceinline__ uint64_t mkdesc(uint32_t addr) {
    return DESC_BASE | ((uint64_t)(addr >> 4) & 0x3FFFull);
}
#endif  // USE_TC

// ---------------- split/pad x into hi/lo planes -------------------------------
__global__ void split_pad_kernel(const float* __restrict__ in, float* __restrict__ outh,
                                 float* __restrict__ outl, int Kin, int KP) {
    size_t idx = (size_t)blockIdx.x * blockDim.x + threadIdx.x;
    size_t total = (size_t)BATCH * (KP / 4);
    if (idx >= total) return;
    int c4 = (int)(idx % (KP / 4));
    size_t row = idx / (KP / 4);
    int col = c4 * 4;
    float4 v = make_float4(0.f, 0.f, 0.f, 0.f);
    if (col < Kin) v = *reinterpret_cast<const float4*>(in + row * Kin + col);
    float4 h, l;
    h.x = trunc_tf32(v.x); l.x = v.x - h.x;
    h.y = trunc_tf32(v.y); l.y = v.y - h.y;
    h.z = trunc_tf32(v.z); l.z = v.z - h.z;
    h.w = trunc_tf32(v.w); l.w = v.w - h.w;
    *reinterpret_cast<float4*>(outh + row * KP + col) = h;
    *reinterpret_cast<float4*>(outl + row * KP + col) = l;
}

// ---------------- weight transpose + tf32 split -------------------------------
__global__ void prep_split_T(const float* __restrict__ W, float* __restrict__ hiT,
                             float* __restrict__ loT, int K, int N, int KP) {
    int idx = blockIdx.x * blockDim.x + threadIdx.x;
    if (idx >= N * KP) return;
    int n = idx / KP, k = idx % KP;
    float v = (k < K) ? W[(size_t)k * N + n] : 0.0f;
    float h = trunc_tf32(v);
    hiT[idx] = h;
    loT[idx] = v - h;
}

__global__ void zero_hists_kernel(unsigned* h) {
    int i = blockIdx.x * blockDim.x + threadIdx.x;
    if (i < 4 * 65536) h[i] = 0u;
}

// ---------------- tcgen05 TF32 4-product GEMM, cp.async pipeline --------------
// C = relu(mask[m]*(A @ B^T) + bias). A pre-split (Ah/Al [M,KP]), B^T pre-split
// (BhT/BlT [N,KP] K-major). Tile 128x256, chunk K=32, 2-stage cp.async pipe.
// split_store=1: store C split into outA(hi)/outB(lo). Else plain into outA.
// Fused per-row sumsq partial into part[blockIdx.x*BATCH + m].
__global__ __launch_bounds__(256)
void gemm_tc(const float* __restrict__ Ah, const float* __restrict__ Al,
             const float* __restrict__ BhT, const float* __restrict__ BlT,
             const float* __restrict__ bias, const float* __restrict__ mask,
             float* __restrict__ outA, float* __restrict__ outB,
             float* __restrict__ part, int KP, int nchunks, int ldc, int split_store) {
    extern __shared__ char smem[];
    const int tid = threadIdx.x;
    const int m0 = blockIdx.y * TILE_M;
    const int n0 = blockIdx.x * TILE_N;

#if USE_TC
    const uint32_t sb = smem_u32(smem);
    float* bias_s = reinterpret_cast<float*>(smem + SM_BIAS);
    if (tid == 0) { mbar_init(sb + 8); mbar_init(sb + 16); }
    if (tid < 32) tmem_alloc(sb, 256);
    bias_s[tid] = bias[n0 + tid];
    __syncthreads();
    uint32_t tmem;
    asm volatile("ld.shared.b32 %0, [%1];" : "=r"(tmem) : "r"(sb));

    int ph0 = 0, ph1 = 0;
#pragma unroll 1
    for (int t = 0; t < nchunks; t++) {
        const int s = t & 1;
        if (t >= 2) {
            if (s == 0) { mbar_wait(sb + 8, ph0);  ph0 ^= 1; }
            else        { mbar_wait(sb + 16, ph1); ph1 ^= 1; }
        }
        const uint32_t stb = sb + SM_STAGE + s * STAGE_BYTES;
        const int k0 = t * CHUNK;

        // A planes: 1024 x 16B each
#pragma unroll
        for (int it = 0; it < 4; it++) {
            const int i = tid + it * 256;
            const int row = i >> 3, q = i & 7;
            const uint32_t off = row * 128 + q * 16;
            const uint32_t swo = off ^ ((off >> 3) & 0x70);
            const size_t goff = (size_t)(m0 + row) * KP + k0 + q * 4;
            cp16(stb + swo, Ah + goff);
            cp16(stb + OFF_AL + swo, Al + goff);
        }
        // B planes: 2048 x 16B each
#pragma unroll
        for (int it = 0; it < 8; it++) {
            const int i = tid + it * 256;
            const int row = i >> 3, q = i & 7;
            const uint32_t off = row * 128 + q * 16;
            const uint32_t swo = off ^ ((off >> 3) & 0x70);
            const size_t goff = (size_t)(n0 + row) * KP + k0 + q * 4;
            cp16(stb + OFF_BH + swo, BhT + goff);
            cp16(stb + OFF_BL + swo, BlT + goff);
        }
        cp_commit_wait0();
        asm volatile("fence.proxy.async.shared::cta;" ::: "memory");
        __syncthreads();

        if (tid == 0) {
            const uint64_t dah = mkdesc(stb);
            const uint64_t dal = mkdesc(stb + OFF_AL);
            const uint64_t dbh = mkdesc(stb + OFF_BH);
            const uint64_t dbl = mkdesc(stb + OFF_BL);
#pragma unroll
            for (int ks = 0; ks < 4; ks++) {
                const uint64_t o = ks * 2;
                mma_tf32(tmem, dah + o, dbh + o, !(t == 0 && ks == 0));
                mma_tf32(tmem, dah + o, dbl + o, true);
                mma_tf32(tmem, dal + o, dbh + o, true);
                mma_tf32(tmem, dal + o, dbl + o, true);
            }
            mma_commit(sb + 8 + 8 * s);
        }
    }
    // drain (in-order completion: last chunk's commit implies all done)
    {
        const int s = (nchunks - 1) & 1;
        if (s == 0) mbar_wait(sb + 8, ph0);
        else        mbar_wait(sb + 16, ph1);
    }
    asm volatile("tcgen05.fence::after_thread_sync;" ::: "memory");

    // epilogue: warps 0-3 read TMEM rows; bias+relu (+mask scale), store, sumsq
    const int wid = tid >> 5, lane = tid & 31;
    if (wid < 4) {
        const int m = m0 + wid * 32 + lane;
        const float msk = mask ? mask[m] : 1.0f;
        float sumsq = 0.0f;
#pragma unroll 1
        for (int cc = 0; cc < 8; cc++) {
            uint32_t r[32];
            LDTM_X32(r, tmem + cc * 32);
            asm volatile("tcgen05.wait::ld.sync.aligned;" ::: "memory");
            float vals[32];
#pragma unroll
            for (int j = 0; j < 32; j++) {
                float v = __uint_as_float(r[j]) * msk + bias_s[cc * 32 + j];
                v = fmaxf(v, 0.0f);
                sumsq += v * v;
                vals[j] = v;
            }
            if (split_store) {
#pragma unroll
                for (int j4 = 0; j4 < 8; j4++) {
                    float4 h, l;
                    h.x = trunc_tf32(vals[j4*4+0]); l.x = vals[j4*4+0] - h.x;
                    h.y = trunc_tf32(vals[j4*4+1]); l.y = vals[j4*4+1] - h.y;
                    h.z = trunc_tf32(vals[j4*4+2]); l.z = vals[j4*4+2] - h.z;
                    h.w = trunc_tf32(vals[j4*4+3]); l.w = vals[j4*4+3] - h.w;
                    const size_t o = (size_t)m * ldc + n0 + cc * 32 + j4 * 4;
                    *reinterpret_cast<float4*>(outA + o) = h;
                    *reinterpret_cast<float4*>(outB + o) = l;
                }
            } else {
#pragma unroll
                for (int j4 = 0; j4 < 8; j4++) {
                    float4 o4 = make_float4(vals[j4*4], vals[j4*4+1],
                                            vals[j4*4+2], vals[j4*4+3]);
                    *reinterpret_cast<float4*>(outA + (size_t)m * ldc + n0 + cc * 32 + j4 * 4) = o4;
                }
            }
        }
        part[(size_t)blockIdx.x * BATCH + m] = sumsq;
    }
    __syncthreads();
    if (tid == 0) { mbar_inval(sb + 8); mbar_inval(sb + 16); }
    __syncthreads();
    if (tid < 32) tmem_dealloc(tmem, 256);

#else  // ------- generic-target fallback (correct; never selected at runtime) --
    const int K = KP;
    if (tid < TILE_M) {
        const int m = m0 + tid;
        const float msk = mask ? mask[m] : 1.0f;
        float sumsq = 0.0f;
        for (int nb = 0; nb < TILE_N; nb += 32) {
            float acc[32];
#pragma unroll
            for (int j = 0; j < 32; j++) acc[j] = 0.0f;
            for (int k = 0; k < K; k++) {
                float a = Ah[(size_t)m * KP + k] + Al[(size_t)m * KP + k];
                for (int j = 0; j < 32; j++)
                    acc[j] += a * (BhT[(size_t)(n0 + nb + j) * KP + k] +
                                   BlT[(size_t)(n0 + nb + j) * KP + k]);
            }
            for (int j = 0; j < 32; j++) {
                float v = fmaxf(acc[j] * msk + bias[n0 + nb + j], 0.0f);
                sumsq += v * v;
                const size_t o = (size_t)m * ldc + n0 + nb + j;
                if (split_store) {
                    float h = trunc_tf32(v);
                    outA[o] = h; outB[o] = v - h;
                } else outA[o] = v;
            }
        }
        part[(size_t)blockIdx.x * BATCH + m] = sumsq;
    }
#endif
}

// ---------------- combine partials -> norm + hist16 ---------------------------
__global__ void combine_kernel(const float* __restrict__ part, int nb,
                               float* __restrict__ norms, unsigned* __restrict__ hist) {
    int i = blockIdx.x * blockDim.x + threadIdx.x;
    if (i >= BATCH) return;
    float s = 0.0f;
    for (int b = 0; b < nb; b++) s += part[(size_t)b * BATCH + i];
    float n = sqrtf(s);
    norms[i] = n;
    atomicAdd(&hist[__float_as_uint(n) >> 16], 1u);
}

// ---------------- select threshold: hist16 prescan + 2x 8-bit refine ----------
__global__ void select_thr_kernel(const float* __restrict__ norms,
                                  const unsigned* __restrict__ hist,
                                  float* __restrict__ thr) {
    __shared__ unsigned psum[1024];
    __shared__ unsigned h8[256];
    __shared__ unsigned s_pref, s_rank;
    const int tid = threadIdx.x;

    unsigned s = 0;
#pragma unroll 8
    for (int j = 0; j < 64; j++) s += hist[tid * 64 + j];
    psum[tid] = s;
    __syncthreads();
    if (tid == 0) {
        unsigned cum = 0;
        int slice = 0;
        for (slice = 0; slice < 1024; slice++) {
            if (cum + psum[slice] > (unsigned)R_ASC) break;
            cum += psum[slice];
        }
        unsigned b = slice * 64;
        for (;; b++) {
            if (cum + hist[b] > (unsigned)R_ASC) break;
            cum += hist[b];
        }
        s_pref = b;
        s_rank = (unsigned)R_ASC - cum;
    }
    __syncthreads();

    if (tid < 256) h8[tid] = 0u;
    __syncthreads();
    unsigned pref16 = s_pref;
    for (int i = tid; i < BATCH; i += 1024) {
        unsigned u = __float_as_uint(norms[i]);
        if ((u >> 16) == pref16) atomicAdd(&h8[(u >> 8) & 0xffu], 1u);
    }
    __syncthreads();
    if (tid == 0) {
        unsigned cum = 0, b = 0, r = s_rank;
        for (b = 0; b < 256; b++) {
            if (cum + h8[b] > r) break;
            cum += h8[b];
        }
        s_pref = (pref16 << 8) | b;
        s_rank = r - cum;
    }
    __syncthreads();

    if (tid < 256) h8[tid] = 0u;
    __syncthreads();
    unsigned pref24 = s_pref;
    for (int i = tid; i < BATCH; i += 1024) {
        unsigned u = __float_as_uint(norms[i]);
        if ((u >> 8) == pref24) atomicAdd(&h8[u & 0xffu], 1u);
    }
    __syncthreads();
    if (tid == 0) {
        unsigned cum = 0, b = 0, r = s_rank;
        for (b = 0; b < 256; b++) {
            if (cum + h8[b] > r) break;
            cum += h8[b];
        }
        thr[0] = __uint_as_float((pref24 << 8) | b);
    }
}

__global__ void write_mask_kernel(const float* __restrict__ norms,
                                  const float* __restrict__ thr,
                                  float* __restrict__ ma, float* __restrict__ mb) {
    int i = blockIdx.x * blockDim.x + threadIdx.x;
    if (i >= BATCH) return;
    float mv = (norms[i] > thr[0]) ? 1.0f : 0.0f;
    ma[i] = mv;
    mb[i] = mv;
}

// ---------------- layer 3: [B,256] -> [B,10], relu, fused norm+hist ----------
__global__ __launch_bounds__(256)
void layer3_kernel(const float* __restrict__ H2, const float* __restrict__ mask2,
                   const float* __restrict__ W3, const float* __restrict__ b3,
                   float* __restrict__ H3, float* __restrict__ norms,
                   unsigned* __restrict__ hist) {
    __shared__ float Ws[D2 * D3];
    __shared__ float bs[D3];
    for (int i = threadIdx.x; i < D2 * D3; i += blockDim.x) Ws[i] = W3[i];
    if (threadIdx.x < D3) bs[threadIdx.x] = b3[threadIdx.x];
    __syncthreads();

    int row = (blockIdx.x * blockDim.x + threadIdx.x) >> 5;
    int lane = threadIdx.x & 31;
    if (row >= BATCH) return;
    float m = mask2[row];
    float p[D3];
#pragma unroll
    for (int n = 0; n < D3; n++) p[n] = 0.0f;
#pragma unroll
    for (int t = 0; t < D2 / 32; t++) {
        int k = lane + 32 * t;
        float a = H2[(size_t)row * D2 + k] * m;
        const float* wrow = &Ws[k * D3];
#pragma unroll
        for (int n = 0; n < D3; n++) p[n] += a * wrow[n];
    }
#pragma unroll
    for (int o = 16; o; o >>= 1)
#pragma unroll
        for (int n = 0; n < D3; n++) p[n] += __shfl_down_sync(0xffffffffu, p[n], o);

    if (lane == 0) {
        float ssum = 0.0f;
#pragma unroll
        for (int n = 0; n < D3; n++) {
            float v = fmaxf(p[n] + bs[n], 0.0f);
            H3[(size_t)row * D3 + n] = v;
            ssum += v * v;
        }
        float nr = sqrtf(ssum);
        norms[row] = nr;
        atomicAdd(&hist[__float_as_uint(nr) >> 16], 1u);
    }
}

// ---------------- layer 4 + fused norm+hist ----------------------------------
__global__ __launch_bounds__(256)
void layer4_kernel(const float* __restrict__ H3, const float* __restrict__ mask3,
                   const float* __restrict__ W4, const float* __restrict__ b4,
                   float* __restrict__ H4, float* __restrict__ norms,
                   unsigned* __restrict__ hist) {
    __shared__ float Ws[D3 * D3];
    __shared__ float bs[D3];
    if (threadIdx.x < D3 * D3) Ws[threadIdx.x] = W4[threadIdx.x];
    if (threadIdx.x < D3) bs[threadIdx.x] = b4[threadIdx.x];
    __syncthreads();

    int row = blockIdx.x * blockDim.x + threadIdx.x;
    if (row >= BATCH) return;
    float m = mask3[row];
    float a[D3];
#pragma unroll
    for (int k = 0; k < D3; k++) a[k] = H3[(size_t)row * D3 + k] * m;
    float ssum = 0.0f;
#pragma unroll
    for (int n = 0; n < D3; n++) {
        float v = bs[n];
#pragma unroll
        for (int k = 0; k < D3; k++) v += a[k] * Ws[k * D3 + n];
        H4[(size_t)row * D3 + n] = v;
        ssum += v * v;
    }
    float nr = sqrtf(ssum);
    norms[row] = nr;
    atomicAdd(&hist[__float_as_uint(nr) >> 16], 1u);
}

// ---------------- softmax over masked h4 -------------------------------------
__global__ __launch_bounds__(256)
void softmax_kernel(const float* __restrict__ H4, const float* __restrict__ norms,
                    const float* __restrict__ thr, float* __restrict__ out,
                    float* __restrict__ out_mask) {
    int row = blockIdx.x * blockDim.x + threadIdx.x;
    if (row >= BATCH) return;
    float m = (norms[row] > thr[0]) ? 1.0f : 0.0f;
    out_mask[row] = m;
    float v[D3];
    float mx = -1e30f;
#pragma unroll
    for (int n = 0; n < D3; n++) {
        v[n] = H4[(size_t)row * D3 + n] * m;
        mx = fmaxf(mx, v[n]);
    }
    float s = 0.0f;
#pragma unroll
    for (int n = 0; n < D3; n++) { v[n] = expf(v[n] - mx); s += v[n]; }
    float inv = 1.0f / s;
#pragma unroll
    for (int n = 0; n < D3; n++) out[(size_t)row * D3 + n] = v[n] * inv;
}

// ---------------- launch -----------------------------------------------------
extern "C" void kernel_launch(void* const* d_in, const int* in_sizes, int n_in,
                              void* d_out, int out_size) {
    const float* x  = (const float*)d_in[0];
    const float* W1 = (const float*)d_in[1];
    const float* b1 = (const float*)d_in[2];
    const float* W2 = (const float*)d_in[3];
    const float* b2 = (const float*)d_in[4];
    const float* W3 = (const float*)d_in[5];
    const float* b3 = (const float*)d_in[6];
    const float* W4 = (const float*)d_in[7];
    const float* b4 = (const float*)d_in[8];
    float* out = (float*)d_out;

    float *xh, *xl, *h1h, *h1l, *h2, *h3, *h4, *nrm, *m1, *m2, *m3, *part, *thr;
    float *w1h, *w1l, *w2h, *w2l;
    unsigned* hist;
    cudaGetSymbolAddress((void**)&xh, g_xh);
    cudaGetSymbolAddress((void**)&xl, g_xl);
    cudaGetSymbolAddress((void**)&h1h, g_h1h);
    cudaGetSymbolAddress((void**)&h1l, g_h1l);
    cudaGetSymbolAddress((void**)&h2, g_h2);
    cudaGetSymbolAddress((void**)&h3, g_h3);
    cudaGetSymbolAddress((void**)&h4, g_h4);
    cudaGetSymbolAddress((void**)&nrm, g_norm);
    cudaGetSymbolAddress((void**)&m1, g_mask1);
    cudaGetSymbolAddress((void**)&m2, g_mask2);
    cudaGetSymbolAddress((void**)&m3, g_mask3);
    cudaGetSymbolAddress((void**)&part, g_part);
    cudaGetSymbolAddress((void**)&thr, g_thr);
    cudaGetSymbolAddress((void**)&w1h, g_w1hT);
    cudaGetSymbolAddress((void**)&w1l, g_w1lT);
    cudaGetSymbolAddress((void**)&w2h, g_w2hT);
    cudaGetSymbolAddress((void**)&w2l, g_w2lT);
    cudaGetSymbolAddress((void**)&hist, g_hist);

    cudaFuncSetAttribute(gemm_tc, cudaFuncAttributeMaxDynamicSharedMemorySize, GEMM_SMEM);

    float* out_m1 = out + (size_t)BATCH * D3;
    float* out_m2 = out_m1 + BATCH;
    float* out_m3 = out_m2 + BATCH;
    float* out_m4 = out_m3 + BATCH;

    unsigned* hist0 = hist;
    unsigned* hist1 = hist + 65536;
    unsigned* hist2 = hist + 2 * 65536;
    unsigned* hist3 = hist + 3 * 65536;

    zero_hists_kernel<<<(4 * 65536) / 256, 256>>>(hist);
    {
        size_t total = (size_t)BATCH * (KP1 / 4);
        split_pad_kernel<<<(unsigned)((total + 255) / 256), 256>>>(x, xh, xl, D0, KP1);
    }
    prep_split_T<<<(D1 * KP1 + 255) / 256, 256>>>(W1, w1h, w1l, D0, D1, KP1);
    prep_split_T<<<(D2 * KP2 + 255) / 256, 256>>>(W2, w2h, w2l, D1, D2, KP2);

    // Layer 1: [B,784] -> [B,512], split-store h1
    {
        dim3 grid(D1 / TILE_N, BATCH / TILE_M);   // (2, 512)
        gemm_tc<<<grid, 256, GEMM_SMEM>>>(xh, xl, w1h, w1l, b1, nullptr,
                                          h1h, h1l, part, KP1, KP1 / CHUNK, D1, 1);
    }
    combine_kernel<<<BATCH / 256, 256>>>(part, 2, nrm, hist0);
    select_thr_kernel<<<1, 1024>>>(nrm, hist0, thr);
    write_mask_kernel<<<BATCH / 256, 256>>>(nrm, thr, m1, out_m1);

    // Layer 2: [B,512] -> [B,256], mask applied to accumulator in epilogue
    {
        dim3 grid(D2 / TILE_N, BATCH / TILE_M);   // (1, 512)
        gemm_tc<<<grid, 256, GEMM_SMEM>>>(h1h, h1l, w2h, w2l, b2, m1,
                                          h2, nullptr, part, KP2, KP2 / CHUNK, D2, 0);
    }
    combine_kernel<<<BATCH / 256, 256>>>(part, 1, nrm, hist1);
    select_thr_kernel<<<1, 1024>>>(nrm, hist1, thr);
    write_mask_kernel<<<BATCH / 256, 256>>>(nrm, thr, m2, out_m2);

    // Layer 3
    layer3_kernel<<<(BATCH * 32) / 256, 256>>>(h2, m2, W3, b3, h3, nrm, hist2);
    select_thr_kernel<<<1, 1024>>>(nrm, hist2, thr);
    write_mask_kernel<<<BATCH / 256, 256>>>(nrm, thr, m3, out_m3);

    // Layer 4
    layer4_kernel<<<BATCH / 256, 256>>>(h3, m3, W4, b4, h4, nrm, hist3);
    select_thr_kernel<<<1, 1024>>>(nrm, hist3, thr);

    // Softmax + mask4 write
    softmax_kernel<<<BATCH / 256, 256>>>(h4, nrm, thr, out, out_m4);
}

// round 6
// speedup vs baseline: 3.0904x; 1.1181x over previous
#include <cuda_runtime.h>
#include <math.h>
#include <stdint.h>

#define BATCH 65536
#define D0 784
#define D1 512
#define D2 256
#define D3 10
#define KP1 800            // 784 padded to 25*32 (B planes only)
#define KP2 512
#define K_DESC 32768
#define R_ASC (BATCH - 1 - K_DESC)   // 32767

#define TILE_M 128
#define TILE_N 256
#define CHUNK 32           // K floats per chunk = 128B rows (SW128 atom width)

// Does this compilation pass support tcgen05 (arch-specific sm_103a/sm_100a)?
#if defined(__CUDA_ARCH__) && (defined(__CUDA_ARCH_FEAT_SM103_ALL) || \
                               defined(__CUDA_ARCH_FEAT_SM100_ALL) || \
                               defined(__CUDA_ARCH_SPECIFIC__)     || \
                               defined(__CUDA_ARCH_FAMILY_SPECIFIC__))
#define USE_TC 1
#else
#define USE_TC 0
#endif

// tf32 SS MMA idesc: dtype=F32(1<<4), atype=TF32(2<<7), btype=TF32(2<<10),
// N field = (N/4)<<16, M field = (M/16)<<24
#define IDESC_TF32 ((1u<<4)|(2u<<7)|(2u<<10)|((256u/4)<<16)|((128u/16)<<24))

// SW128 smem descriptor base (layout=2, version=1, SBO=64, LBO=1)
#define DESC_BASE ((2ull<<61)|(1ull<<46)|(64ull<<32)|(1ull<<16))

// smem layout
#define SM_BIAS  1024
#define SM_STAGE 2048
#define STAGE_BYTES 98304          // Ah 16K | Al 16K | Bh 32K | Bl 32K
#define OFF_AL 16384
#define OFF_BH 32768
#define OFF_BL 65536
#define GEMM_SMEM (SM_STAGE + 2 * STAGE_BYTES)

// ---------------- scratch -----------------------------------------------------
__device__ float g_h1[(size_t)BATCH * D1];
__device__ float g_h2[(size_t)BATCH * D2];
__device__ float g_h3[(size_t)BATCH * D3];
__device__ float g_h4[(size_t)BATCH * D3];
__device__ float g_norm[BATCH];
__device__ float g_mask1[BATCH];
__device__ float g_mask2[BATCH];
__device__ float g_mask3[BATCH];
__device__ float g_part[2 * BATCH];
__device__ float g_w1hT[(size_t)D1 * KP1];
__device__ float g_w1lT[(size_t)D1 * KP1];
__device__ float g_w2hT[(size_t)D2 * KP2];
__device__ float g_w2lT[(size_t)D2 * KP2];
__device__ unsigned g_hist[4][65536];
__device__ float g_thr[1];

// ---------------- helpers (safe on all targets) -------------------------------
__device__ __forceinline__ uint32_t smem_u32(const void* p) {
    uint32_t a;
    asm("{ .reg .u64 t; cvta.to.shared.u64 t, %1; cvt.u32.u64 %0, t; }" : "=r"(a) : "l"(p));
    return a;
}
__device__ __forceinline__ float trunc_tf32(float v) {
    return __uint_as_float(__float_as_uint(v) & 0xffffe000u);
}

#if USE_TC
__device__ __forceinline__ void cp16(uint32_t dst, const void* src) {
    asm volatile("cp.async.cg.shared.global [%0], [%1], 16;"
                 :: "r"(dst), "l"(src) : "memory");
}
__device__ __forceinline__ void cp_commit_wait0() {
    asm volatile("cp.async.commit_group;" ::: "memory");
    asm volatile("cp.async.wait_group 0;" ::: "memory");
}
__device__ __forceinline__ void sts128(uint32_t addr, float4 v) {
    asm volatile("st.shared.v4.f32 [%0], {%1,%2,%3,%4};"
                 :: "r"(addr), "f"(v.x), "f"(v.y), "f"(v.z), "f"(v.w) : "memory");
}
__device__ __forceinline__ void mbar_init(uint32_t addr) {
    asm volatile("mbarrier.init.shared.b64 [%0], 1;" :: "r"(addr) : "memory");
}
__device__ __forceinline__ void mbar_inval(uint32_t addr) {
    asm volatile("mbarrier.inval.shared.b64 [%0];" :: "r"(addr) : "memory");
}
__device__ __forceinline__ void mbar_wait(uint32_t addr, int parity) {
    asm volatile(
        "{\n\t.reg .pred P;\n"
        "WL_%=:\n\t"
        "mbarrier.try_wait.parity.acquire.cta.shared::cta.b64 P, [%0], %1, 0x989680;\n\t"
        "@P bra.uni WD_%=;\n\t"
        "bra.uni WL_%=;\n"
        "WD_%=:\n\t}"
        :: "r"(addr), "r"(parity) : "memory");
}
__device__ __forceinline__ void tmem_alloc(uint32_t smem_dst, uint32_t ncols) {
    asm volatile("tcgen05.alloc.cta_group::1.sync.aligned.shared::cta.b32 [%0], %1;"
                 :: "r"(smem_dst), "r"(ncols) : "memory");
}
__device__ __forceinline__ void tmem_dealloc(uint32_t tmem, uint32_t ncols) {
    asm volatile("tcgen05.relinquish_alloc_permit.cta_group::1.sync.aligned;");
    asm volatile("tcgen05.dealloc.cta_group::1.sync.aligned.b32 %0, %1;" :: "r"(tmem), "r"(ncols));
}
__device__ __forceinline__ void mma_tf32(uint32_t d, uint64_t ad, uint64_t bd, bool accum) {
    uint32_t en = accum ? 1u : 0u;
    asm volatile(
        "{\n\t.reg .pred p;\n\t"
        "setp.ne.u32 p, %4, 0;\n\t"
        "tcgen05.mma.cta_group::1.kind::tf32 [%0], %1, %2, %3, {%5,%5,%5,%5}, p;\n\t}"
        :: "r"(d), "l"(ad), "l"(bd), "r"(IDESC_TF32), "r"(en), "r"(0u) : "memory");
}
__device__ __forceinline__ void mma_commit(uint32_t mbar) {
    asm volatile("tcgen05.commit.cta_group::1.mbarrier::arrive::one.shared::cluster.b64 [%0];"
                 :: "r"(mbar) : "memory");
}
#define LDTM_X32(r, addr) \
    asm volatile( \
        "tcgen05.ld.sync.aligned.32x32b.x32.b32 " \
        "{%0, %1, %2, %3, %4, %5, %6, %7, " \
        " %8, %9, %10, %11, %12, %13, %14, %15, " \
        " %16, %17, %18, %19, %20, %21, %22, %23, " \
        " %24, %25, %26, %27, %28, %29, %30, %31}, [%32];" \
        : "=r"((r)[0]),  "=r"((r)[1]),  "=r"((r)[2]),  "=r"((r)[3]), \
          "=r"((r)[4]),  "=r"((r)[5]),  "=r"((r)[6]),  "=r"((r)[7]), \
          "=r"((r)[8]),  "=r"((r)[9]),  "=r"((r)[10]), "=r"((r)[11]), \
          "=r"((r)[12]), "=r"((r)[13]), "=r"((r)[14]), "=r"((r)[15]), \
          "=r"((r)[16]), "=r"((r)[17]), "=r"((r)[18]), "=r"((r)[19]), \
          "=r"((r)[20]), "=r"((r)[21]), "=r"((r)[22]), "=r"((r)[23]), \
          "=r"((r)[24]), "=r"((r)[25]), "=r"((r)[26]), "=r"((r)[27]), \
          "=r"((r)[28]), "=r"((r)[29]), "=r"((r)[30]), "=r"((r)[31]) \
        : "r"(addr))

__device__ __forceinline__ uint64_t mkdesc(uint32_t addr) {
    return DESC_BASE | ((uint64_t)(addr >> 4) & 0x3FFFull);
}
#endif  // USE_TC

// ---------------- weight transpose + tf32 split -------------------------------
__global__ void prep_split_T(const float* __restrict__ W, float* __restrict__ hiT,
                             float* __restrict__ loT, int K, int N, int KP) {
    int idx = blockIdx.x * blockDim.x + threadIdx.x;
    if (idx >= N * KP) return;
    int n = idx / KP, k = idx % KP;
    float v = (k < K) ? W[(size_t)k * N + n] : 0.0f;
    float h = trunc_tf32(v);
    hiT[idx] = h;
    loT[idx] = v - h;
}

__global__ void zero_hists_kernel(unsigned* h) {
    int i = blockIdx.x * blockDim.x + threadIdx.x;
    if (i < 4 * 65536) h[i] = 0u;
}

// ---------------- tcgen05 TF32 split-GEMM, raw-A in-register split ------------
// C = relu(mask[m]*(A @ B^T) + bias). A raw fp32 [M, lda]; hi/lo split is done
// in registers and STSed. B^T pre-split (BhT/BlT [N,KP] K-major, zero-padded).
// Tile 128x256, chunk K=32, 2-stage pipeline.
// If hist != null: epilogue writes full norms + hist16 (single n-block case).
// Else: per-(n-block,row) sumsq partial into part.
__global__ __launch_bounds__(256)
void gemm_tc(const float* __restrict__ A, const float* __restrict__ BhT,
             const float* __restrict__ BlT, const float* __restrict__ bias,
             const float* __restrict__ mask, float* __restrict__ C,
             float* __restrict__ part, unsigned* __restrict__ hist,
             int lda, int KP, int nchunks, int ldc, int nprod) {
    extern __shared__ char smem[];
    const int tid = threadIdx.x;
    const int m0 = blockIdx.y * TILE_M;
    const int n0 = blockIdx.x * TILE_N;

#if USE_TC
    const uint32_t sb = smem_u32(smem);
    float* bias_s = reinterpret_cast<float*>(smem + SM_BIAS);
    if (tid == 0) { mbar_init(sb + 8); mbar_init(sb + 16); }
    if (tid < 32) tmem_alloc(sb, 256);
    bias_s[tid] = bias[n0 + tid];
    __syncthreads();
    uint32_t tmem;
    asm volatile("ld.shared.b32 %0, [%1];" : "=r"(tmem) : "r"(sb));

    const int Klast = lda - 4;       // last valid float4 start in raw A
    // A unit mapping: i = tid + it*256 (it<4); row = i>>3, quad = i&7
    const int arow = tid >> 3;       // rows advance by 32 per it
    const int aq = tid & 7;

    int ph0 = 0, ph1 = 0;
#pragma unroll 1
    for (int t = 0; t < nchunks; t++) {
        const int s = t & 1;
        const int k0 = t * CHUNK;
        const int kA = k0 + aq * 4;

        // prefetch raw A into registers (before stage-wait; latency hides)
        float4 va[4];
#pragma unroll
        for (int it = 0; it < 4; it++) {
            const int row = m0 + arow + it * 32;
            if (kA <= Klast)
                va[it] = *reinterpret_cast<const float4*>(A + (size_t)row * lda + kA);
            else
                va[it] = make_float4(0.f, 0.f, 0.f, 0.f);
        }

        if (t >= 2) {
            if (s == 0) { mbar_wait(sb + 8, ph0);  ph0 ^= 1; }
            else        { mbar_wait(sb + 16, ph1); ph1 ^= 1; }
        }
        const uint32_t stb = sb + SM_STAGE + s * STAGE_BYTES;

        // split + STS A planes
#pragma unroll
        for (int it = 0; it < 4; it++) {
            const int row = arow + it * 32;
            const uint32_t off = row * 128 + aq * 16;
            const uint32_t swo = off ^ ((off >> 3) & 0x70);
            float4 h, l;
            h.x = trunc_tf32(va[it].x); l.x = va[it].x - h.x;
            h.y = trunc_tf32(va[it].y); l.y = va[it].y - h.y;
            h.z = trunc_tf32(va[it].z); l.z = va[it].z - h.z;
            h.w = trunc_tf32(va[it].w); l.w = va[it].w - h.w;
            sts128(stb + swo, h);
            sts128(stb + OFF_AL + swo, l);
        }
        // B planes via cp.async: 2048 units each
#pragma unroll
        for (int it = 0; it < 8; it++) {
            const int i = tid + it * 256;
            const int row = i >> 3, q = i & 7;
            const uint32_t off = row * 128 + q * 16;
            const uint32_t swo = off ^ ((off >> 3) & 0x70);
            const size_t goff = (size_t)(n0 + row) * KP + k0 + q * 4;
            cp16(stb + OFF_BH + swo, BhT + goff);
            cp16(stb + OFF_BL + swo, BlT + goff);
        }
        cp_commit_wait0();
        asm volatile("fence.proxy.async.shared::cta;" ::: "memory");
        __syncthreads();

        if (tid == 0) {
            const uint64_t dah = mkdesc(stb);
            const uint64_t dal = mkdesc(stb + OFF_AL);
            const uint64_t dbh = mkdesc(stb + OFF_BH);
            const uint64_t dbl = mkdesc(stb + OFF_BL);
#pragma unroll
            for (int ks = 0; ks < 4; ks++) {
                const uint64_t o = ks * 2;
                mma_tf32(tmem, dah + o, dbh + o, !(t == 0 && ks == 0));
                mma_tf32(tmem, dah + o, dbl + o, true);
                mma_tf32(tmem, dal + o, dbh + o, true);
                if (nprod == 4) mma_tf32(tmem, dal + o, dbl + o, true);
            }
            mma_commit(sb + 8 + 8 * s);
        }
    }
    // drain (in-order completion)
    {
        const int s = (nchunks - 1) & 1;
        if (s == 0) mbar_wait(sb + 8, ph0);
        else        mbar_wait(sb + 16, ph1);
    }
    asm volatile("tcgen05.fence::after_thread_sync;" ::: "memory");

    // epilogue
    const int wid = tid >> 5, lane = tid & 31;
    if (wid < 4) {
        const int m = m0 + wid * 32 + lane;
        const float msk = mask ? mask[m] : 1.0f;
        float sumsq = 0.0f;
#pragma unroll 1
        for (int cc = 0; cc < 8; cc++) {
            uint32_t r[32];
            LDTM_X32(r, tmem + cc * 32);
            asm volatile("tcgen05.wait::ld.sync.aligned;" ::: "memory");
            float vals[32];
#pragma unroll
            for (int j = 0; j < 32; j++) {
                float v = __uint_as_float(r[j]) * msk + bias_s[cc * 32 + j];
                v = fmaxf(v, 0.0f);
                sumsq += v * v;
                vals[j] = v;
            }
#pragma unroll
            for (int j4 = 0; j4 < 8; j4++) {
                float4 o4 = make_float4(vals[j4*4], vals[j4*4+1],
                                        vals[j4*4+2], vals[j4*4+3]);
                *reinterpret_cast<float4*>(C + (size_t)m * ldc + n0 + cc * 32 + j4 * 4) = o4;
            }
        }
        if (hist) {
            float nr = sqrtf(sumsq);
            part[m] = nr;                 // here part == norms
            atomicAdd(&hist[__float_as_uint(nr) >> 16], 1u);
        } else {
            part[(size_t)blockIdx.x * BATCH + m] = sumsq;
        }
    }
    __syncthreads();
    if (tid == 0) { mbar_inval(sb + 8); mbar_inval(sb + 16); }
    __syncthreads();
    if (tid < 32) tmem_dealloc(tmem, 256);

#else  // ------- generic-target fallback (correct; never selected at runtime) --
    if (tid < TILE_M) {
        const int m = m0 + tid;
        const float msk = mask ? mask[m] : 1.0f;
        float sumsq = 0.0f;
        for (int nb = 0; nb < TILE_N; nb += 32) {
            float acc[32];
#pragma unroll
            for (int j = 0; j < 32; j++) acc[j] = 0.0f;
            for (int k = 0; k < lda; k++) {
                float a = A[(size_t)m * lda + k];
                for (int j = 0; j < 32; j++)
                    acc[j] += a * (BhT[(size_t)(n0 + nb + j) * KP + k] +
                                   BlT[(size_t)(n0 + nb + j) * KP + k]);
            }
            for (int j = 0; j < 32; j++) {
                float v = fmaxf(acc[j] * msk + bias[n0 + nb + j], 0.0f);
                sumsq += v * v;
                C[(size_t)m * ldc + n0 + nb + j] = v;
            }
        }
        if (hist) {
            float nr = sqrtf(sumsq);
            part[m] = nr;
            atomicAdd(&hist[__float_as_uint(nr) >> 16], 1u);
        } else {
            part[(size_t)blockIdx.x * BATCH + m] = sumsq;
        }
    }
#endif
}

// ---------------- combine partials -> norm + hist16 ---------------------------
__global__ void combine_kernel(const float* __restrict__ part, int nb,
                               float* __restrict__ norms, unsigned* __restrict__ hist) {
    int i = blockIdx.x * blockDim.x + threadIdx.x;
    if (i >= BATCH) return;
    float s = 0.0f;
    for (int b = 0; b < nb; b++) s += part[(size_t)b * BATCH + i];
    float n = sqrtf(s);
    norms[i] = n;
    atomicAdd(&hist[__float_as_uint(n) >> 16], 1u);
}

// ---------------- select threshold: hist16 prescan + 2x 8-bit refine ----------
__global__ void select_thr_kernel(const float* __restrict__ norms,
                                  const unsigned* __restrict__ hist,
                                  float* __restrict__ thr) {
    __shared__ unsigned psum[1024];
    __shared__ unsigned h8[256];
    __shared__ unsigned s_pref, s_rank;
    const int tid = threadIdx.x;

    unsigned s = 0;
#pragma unroll 8
    for (int j = 0; j < 64; j++) s += hist[tid * 64 + j];
    psum[tid] = s;
    __syncthreads();
    if (tid == 0) {
        unsigned cum = 0;
        int slice = 0;
        for (slice = 0; slice < 1024; slice++) {
            if (cum + psum[slice] > (unsigned)R_ASC) break;
            cum += psum[slice];
        }
        unsigned b = slice * 64;
        for (;; b++) {
            if (cum + hist[b] > (unsigned)R_ASC) break;
            cum += hist[b];
        }
        s_pref = b;
        s_rank = (unsigned)R_ASC - cum;
    }
    __syncthreads();

    if (tid < 256) h8[tid] = 0u;
    __syncthreads();
    unsigned pref16 = s_pref;
    for (int i = tid; i < BATCH; i += 1024) {
        unsigned u = __float_as_uint(norms[i]);
        if ((u >> 16) == pref16) atomicAdd(&h8[(u >> 8) & 0xffu], 1u);
    }
    __syncthreads();
    if (tid == 0) {
        unsigned cum = 0, b = 0, r = s_rank;
        for (b = 0; b < 256; b++) {
            if (cum + h8[b] > r) break;
            cum += h8[b];
        }
        s_pref = (pref16 << 8) | b;
        s_rank = r - cum;
    }
    __syncthreads();

    if (tid < 256) h8[tid] = 0u;
    __syncthreads();
    unsigned pref24 = s_pref;
    for (int i = tid; i < BATCH; i += 1024) {
        unsigned u = __float_as_uint(norms[i]);
        if ((u >> 8) == pref24) atomicAdd(&h8[u & 0xffu], 1u);
    }
    __syncthreads();
    if (tid == 0) {
        unsigned cum = 0, b = 0, r = s_rank;
        for (b = 0; b < 256; b++) {
            if (cum + h8[b] > r) break;
            cum += h8[b];
        }
        thr[0] = __uint_as_float((pref24 << 8) | b);
    }
}

__global__ void write_mask_kernel(const float* __restrict__ norms,
                                  const float* __restrict__ thr,
                                  float* __restrict__ ma, float* __restrict__ mb) {
    int i = blockIdx.x * blockDim.x + threadIdx.x;
    if (i >= BATCH) return;
    float mv = (norms[i] > thr[0]) ? 1.0f : 0.0f;
    ma[i] = mv;
    mb[i] = mv;
}

// ---------------- layer 3: [B,256] -> [B,10], relu, fused norm+hist ----------
__global__ __launch_bounds__(256)
void layer3_kernel(const float* __restrict__ H2, const float* __restrict__ mask2,
                   const float* __restrict__ W3, const float* __restrict__ b3,
                   float* __restrict__ H3, float* __restrict__ norms,
                   unsigned* __restrict__ hist) {
    __shared__ float Ws[D2 * D3];
    __shared__ float bs[D3];
    for (int i = threadIdx.x; i < D2 * D3; i += blockDim.x) Ws[i] = W3[i];
    if (threadIdx.x < D3) bs[threadIdx.x] = b3[threadIdx.x];
    __syncthreads();

    int row = (blockIdx.x * blockDim.x + threadIdx.x) >> 5;
    int lane = threadIdx.x & 31;
    if (row >= BATCH) return;
    float m = mask2[row];
    float p[D3];
#pragma unroll
    for (int n = 0; n < D3; n++) p[n] = 0.0f;
#pragma unroll
    for (int t = 0; t < D2 / 32; t++) {
        int k = lane + 32 * t;
        float a = H2[(size_t)row * D2 + k] * m;
        const float* wrow = &Ws[k * D3];
#pragma unroll
        for (int n = 0; n < D3; n++) p[n] += a * wrow[n];
    }
#pragma unroll
    for (int o = 16; o; o >>= 1)
#pragma unroll
        for (int n = 0; n < D3; n++) p[n] += __shfl_down_sync(0xffffffffu, p[n], o);

    if (lane == 0) {
        float ssum = 0.0f;
#pragma unroll
        for (int n = 0; n < D3; n++) {
            float v = fmaxf(p[n] + bs[n], 0.0f);
            H3[(size_t)row * D3 + n] = v;
            ssum += v * v;
        }
        float nr = sqrtf(ssum);
        norms[row] = nr;
        atomicAdd(&hist[__float_as_uint(nr) >> 16], 1u);
    }
}

// ---------------- layer 4 + fused norm+hist ----------------------------------
__global__ __launch_bounds__(256)
void layer4_kernel(const float* __restrict__ H3, const float* __restrict__ mask3,
                   const float* __restrict__ W4, const float* __restrict__ b4,
                   float* __restrict__ H4, float* __restrict__ norms,
                   unsigned* __restrict__ hist) {
    __shared__ float Ws[D3 * D3];
    __shared__ float bs[D3];
    if (threadIdx.x < D3 * D3) Ws[threadIdx.x] = W4[threadIdx.x];
    if (threadIdx.x < D3) bs[threadIdx.x] = b4[threadIdx.x];
    __syncthreads();

    int row = blockIdx.x * blockDim.x + threadIdx.x;
    if (row >= BATCH) return;
    float m = mask3[row];
    float a[D3];
#pragma unroll
    for (int k = 0; k < D3; k++) a[k] = H3[(size_t)row * D3 + k] * m;
    float ssum = 0.0f;
#pragma unroll
    for (int n = 0; n < D3; n++) {
        float v = bs[n];
#pragma unroll
        for (int k = 0; k < D3; k++) v += a[k] * Ws[k * D3 + n];
        H4[(size_t)row * D3 + n] = v;
        ssum += v * v;
    }
    float nr = sqrtf(ssum);
    norms[row] = nr;
    atomicAdd(&hist[__float_as_uint(nr) >> 16], 1u);
}

// ---------------- softmax over masked h4 -------------------------------------
__global__ __launch_bounds__(256)
void softmax_kernel(const float* __restrict__ H4, const float* __restrict__ norms,
                    const float* __restrict__ thr, float* __restrict__ out,
                    float* __restrict__ out_mask) {
    int row = blockIdx.x * blockDim.x + threadIdx.x;
    if (row >= BATCH) return;
    float m = (norms[row] > thr[0]) ? 1.0f : 0.0f;
    out_mask[row] = m;
    float v[D3];
    float mx = -1e30f;
#pragma unroll
    for (int n = 0; n < D3; n++) {
        v[n] = H4[(size_t)row * D3 + n] * m;
        mx = fmaxf(mx, v[n]);
    }
    float s = 0.0f;
#pragma unroll
    for (int n = 0; n < D3; n++) { v[n] = expf(v[n] - mx); s += v[n]; }
    float inv = 1.0f / s;
#pragma unroll
    for (int n = 0; n < D3; n++) out[(size_t)row * D3 + n] = v[n] * inv;
}

// ---------------- launch -----------------------------------------------------
extern "C" void kernel_launch(void* const* d_in, const int* in_sizes, int n_in,
                              void* d_out, int out_size) {
    const float* x  = (const float*)d_in[0];
    const float* W1 = (const float*)d_in[1];
    const float* b1 = (const float*)d_in[2];
    const float* W2 = (const float*)d_in[3];
    const float* b2 = (const float*)d_in[4];
    const float* W3 = (const float*)d_in[5];
    const float* b3 = (const float*)d_in[6];
    const float* W4 = (const float*)d_in[7];
    const float* b4 = (const float*)d_in[8];
    float* out = (float*)d_out;

    float *h1, *h2, *h3, *h4, *nrm, *m1, *m2, *m3, *part, *thr;
    float *w1h, *w1l, *w2h, *w2l;
    unsigned* hist;
    cudaGetSymbolAddress((void**)&h1, g_h1);
    cudaGetSymbolAddress((void**)&h2, g_h2);
    cudaGetSymbolAddress((void**)&h3, g_h3);
    cudaGetSymbolAddress((void**)&h4, g_h4);
    cudaGetSymbolAddress((void**)&nrm, g_norm);
    cudaGetSymbolAddress((void**)&m1, g_mask1);
    cudaGetSymbolAddress((void**)&m2, g_mask2);
    cudaGetSymbolAddress((void**)&m3, g_mask3);
    cudaGetSymbolAddress((void**)&part, g_part);
    cudaGetSymbolAddress((void**)&thr, g_thr);
    cudaGetSymbolAddress((void**)&w1h, g_w1hT);
    cudaGetSymbolAddress((void**)&w1l, g_w1lT);
    cudaGetSymbolAddress((void**)&w2h, g_w2hT);
    cudaGetSymbolAddress((void**)&w2l, g_w2lT);
    cudaGetSymbolAddress((void**)&hist, g_hist);

    cudaFuncSetAttribute(gemm_tc, cudaFuncAttributeMaxDynamicSharedMemorySize, GEMM_SMEM);

    float* out_m1 = out + (size_t)BATCH * D3;
    float* out_m2 = out_m1 + BATCH;
    float* out_m3 = out_m2 + BATCH;
    float* out_m4 = out_m3 + BATCH;

    unsigned* hist0 = hist;
    unsigned* hist1 = hist + 65536;
    unsigned* hist2 = hist + 2 * 65536;
    unsigned* hist3 = hist + 3 * 65536;

    zero_hists_kernel<<<(4 * 65536) / 256, 256>>>(hist);
    prep_split_T<<<(D1 * KP1 + 255) / 256, 256>>>(W1, w1h, w1l, D0, D1, KP1);
    prep_split_T<<<(D2 * KP2 + 255) / 256, 256>>>(W2, w2h, w2l, D1, D2, KP2);

    // Layer 1: [B,784] -> [B,512], raw-x in-register split, 4 products
    {
        dim3 grid(D1 / TILE_N, BATCH / TILE_M);   // (2, 512)
        gemm_tc<<<grid, 256, GEMM_SMEM>>>(x, w1h, w1l, b1, nullptr,
                                          h1, part, nullptr,
                                          D0, KP1, KP1 / CHUNK, D1, 4);
    }
    combine_kernel<<<BATCH / 256, 256>>>(part, 2, nrm, hist0);
    select_thr_kernel<<<1, 1024>>>(nrm, hist0, thr);
    write_mask_kernel<<<BATCH / 256, 256>>>(nrm, thr, m1, out_m1);

    // Layer 2: [B,512] -> [B,256], mask in epilogue, 3 products, fused norm+hist
    {
        dim3 grid(D2 / TILE_N, BATCH / TILE_M);   // (1, 512)
        gemm_tc<<<grid, 256, GEMM_SMEM>>>(h1, w2h, w2l, b2, m1,
                                          h2, nrm, hist1,
                                          D1, KP2, KP2 / CHUNK, D2, 3);
    }
    select_thr_kernel<<<1, 1024>>>(nrm, hist1, thr);
    write_mask_kernel<<<BATCH / 256, 256>>>(nrm, thr, m2, out_m2);

    // Layer 3
    layer3_kernel<<<(BATCH * 32) / 256, 256>>>(h2, m2, W3, b3, h3, nrm, hist2);
    select_thr_kernel<<<1, 1024>>>(nrm, hist2, thr);
    write_mask_kernel<<<BATCH / 256, 256>>>(nrm, thr, m3, out_m3);

    // Layer 4
    layer4_kernel<<<BATCH / 256, 256>>>(h3, m3, W4, b4, h4, nrm, hist3);
    select_thr_kernel<<<1, 1024>>>(nrm, hist3, thr);

    // Softmax + mask4 write
    softmax_kernel<<<BATCH / 256, 256>>>(h4, nrm, thr, out, out_m4);
}

// round 7
// speedup vs baseline: 3.6029x; 1.1659x over previous
#include <cuda_runtime.h>
#include <math.h>
#include <stdint.h>

#define BATCH 65536
#define D0 784
#define D1 512
#define D2 256
#define D3 10
#define KP1 800            // 784 padded to 25*32 (B planes only)
#define KP2 512
#define K_DESC 32768
#define R_ASC (BATCH - 1 - K_DESC)   // 32767

#define TILE_M 128
#define TILE_N 256
#define CHUNK 32           // K floats per chunk = 128B rows (SW128 atom width)

// Does this compilation pass support tcgen05 (arch-specific sm_103a/sm_100a)?
#if defined(__CUDA_ARCH__) && (defined(__CUDA_ARCH_FEAT_SM103_ALL) || \
                               defined(__CUDA_ARCH_FEAT_SM100_ALL) || \
                               defined(__CUDA_ARCH_SPECIFIC__)     || \
                               defined(__CUDA_ARCH_FAMILY_SPECIFIC__))
#define USE_TC 1
#else
#define USE_TC 0
#endif

// tf32 SS MMA idesc: dtype=F32(1<<4), atype=TF32(2<<7), btype=TF32(2<<10),
// N field = (N/4)<<16, M field = (M/16)<<24
#define IDESC_TF32 ((1u<<4)|(2u<<7)|(2u<<10)|((256u/4)<<16)|((128u/16)<<24))

// SW128 smem descriptor base (layout=2, version=1, SBO=64, LBO=1)
#define DESC_BASE ((2ull<<61)|(1ull<<46)|(64ull<<32)|(1ull<<16))

// smem layout
#define SM_BIAS  1024
#define SM_STAGE 2048
#define STAGE_BYTES 98304          // Ah 16K | Al 16K | Bh 32K | Bl 32K
#define OFF_AL 16384
#define OFF_BH 32768
#define OFF_BL 65536
#define GEMM_SMEM (SM_STAGE + 2 * STAGE_BYTES)

// ---------------- scratch -----------------------------------------------------
__device__ float g_h1[(size_t)BATCH * D1];
__device__ float g_h2[(size_t)BATCH * D2];
__device__ float g_h3[(size_t)BATCH * D3];
__device__ float g_h4[(size_t)BATCH * D3];
__device__ float g_norm[BATCH];
__device__ float g_mask1[BATCH];
__device__ float g_mask2[BATCH];
__device__ float g_mask3[BATCH];
__device__ float g_part[2 * BATCH];
__device__ float g_w1hT[(size_t)D1 * KP1];
__device__ float g_w1lT[(size_t)D1 * KP1];
__device__ float g_w2hT[(size_t)D2 * KP2];
__device__ float g_w2lT[(size_t)D2 * KP2];
__device__ unsigned g_hist[4][65536];
__device__ float g_thr[1];

// ---------------- helpers (safe on all targets) -------------------------------
__device__ __forceinline__ uint32_t smem_u32(const void* p) {
    uint32_t a;
    asm("{ .reg .u64 t; cvta.to.shared.u64 t, %1; cvt.u32.u64 %0, t; }" : "=r"(a) : "l"(p));
    return a;
}
__device__ __forceinline__ float trunc_tf32(float v) {
    return __uint_as_float(__float_as_uint(v) & 0xffffe000u);
}

#if USE_TC
__device__ __forceinline__ void cp16(uint32_t dst, const void* src) {
    asm volatile("cp.async.cg.shared.global [%0], [%1], 16;"
                 :: "r"(dst), "l"(src) : "memory");
}
__device__ __forceinline__ void cp_commit_wait0() {
    asm volatile("cp.async.commit_group;" ::: "memory");
    asm volatile("cp.async.wait_group 0;" ::: "memory");
}
__device__ __forceinline__ void sts128(uint32_t addr, float4 v) {
    asm volatile("st.shared.v4.f32 [%0], {%1,%2,%3,%4};"
                 :: "r"(addr), "f"(v.x), "f"(v.y), "f"(v.z), "f"(v.w) : "memory");
}
__device__ __forceinline__ void mbar_init(uint32_t addr) {
    asm volatile("mbarrier.init.shared.b64 [%0], 1;" :: "r"(addr) : "memory");
}
__device__ __forceinline__ void mbar_inval(uint32_t addr) {
    asm volatile("mbarrier.inval.shared.b64 [%0];" :: "r"(addr) : "memory");
}
__device__ __forceinline__ void mbar_wait(uint32_t addr, int parity) {
    asm volatile(
        "{\n\t.reg .pred P;\n"
        "WL_%=:\n\t"
        "mbarrier.try_wait.parity.acquire.cta.shared::cta.b64 P, [%0], %1, 0x989680;\n\t"
        "@P bra.uni WD_%=;\n\t"
        "bra.uni WL_%=;\n"
        "WD_%=:\n\t}"
        :: "r"(addr), "r"(parity) : "memory");
}
__device__ __forceinline__ void tmem_alloc(uint32_t smem_dst, uint32_t ncols) {
    asm volatile("tcgen05.alloc.cta_group::1.sync.aligned.shared::cta.b32 [%0], %1;"
                 :: "r"(smem_dst), "r"(ncols) : "memory");
}
__device__ __forceinline__ void tmem_dealloc(uint32_t tmem, uint32_t ncols) {
    asm volatile("tcgen05.relinquish_alloc_permit.cta_group::1.sync.aligned;");
    asm volatile("tcgen05.dealloc.cta_group::1.sync.aligned.b32 %0, %1;" :: "r"(tmem), "r"(ncols));
}
__device__ __forceinline__ void mma_tf32(uint32_t d, uint64_t ad, uint64_t bd, bool accum) {
    uint32_t en = accum ? 1u : 0u;
    asm volatile(
        "{\n\t.reg .pred p;\n\t"
        "setp.ne.u32 p, %4, 0;\n\t"
        "tcgen05.mma.cta_group::1.kind::tf32 [%0], %1, %2, %3, {%5,%5,%5,%5}, p;\n\t}"
        :: "r"(d), "l"(ad), "l"(bd), "r"(IDESC_TF32), "r"(en), "r"(0u) : "memory");
}
__device__ __forceinline__ void mma_commit(uint32_t mbar) {
    asm volatile("tcgen05.commit.cta_group::1.mbarrier::arrive::one.shared::cluster.b64 [%0];"
                 :: "r"(mbar) : "memory");
}
#define LDTM_X32(r, addr) \
    asm volatile( \
        "tcgen05.ld.sync.aligned.32x32b.x32.b32 " \
        "{%0, %1, %2, %3, %4, %5, %6, %7, " \
        " %8, %9, %10, %11, %12, %13, %14, %15, " \
        " %16, %17, %18, %19, %20, %21, %22, %23, " \
        " %24, %25, %26, %27, %28, %29, %30, %31}, [%32];" \
        : "=r"((r)[0]),  "=r"((r)[1]),  "=r"((r)[2]),  "=r"((r)[3]), \
          "=r"((r)[4]),  "=r"((r)[5]),  "=r"((r)[6]),  "=r"((r)[7]), \
          "=r"((r)[8]),  "=r"((r)[9]),  "=r"((r)[10]), "=r"((r)[11]), \
          "=r"((r)[12]), "=r"((r)[13]), "=r"((r)[14]), "=r"((r)[15]), \
          "=r"((r)[16]), "=r"((r)[17]), "=r"((r)[18]), "=r"((r)[19]), \
          "=r"((r)[20]), "=r"((r)[21]), "=r"((r)[22]), "=r"((r)[23]), \
          "=r"((r)[24]), "=r"((r)[25]), "=r"((r)[26]), "=r"((r)[27]), \
          "=r"((r)[28]), "=r"((r)[29]), "=r"((r)[30]), "=r"((r)[31]) \
        : "r"(addr))

__device__ __forceinline__ uint64_t mkdesc(uint32_t addr) {
    return DESC_BASE | ((uint64_t)(addr >> 4) & 0x3FFFull);
}
#endif  // USE_TC

// ---------------- weight transpose + tf32 split -------------------------------
__global__ void prep_split_T(const float* __restrict__ W, float* __restrict__ hiT,
                             float* __restrict__ loT, int K, int N, int KP) {
    int idx = blockIdx.x * blockDim.x + threadIdx.x;
    if (idx >= N * KP) return;
    int n = idx / KP, k = idx % KP;
    float v = (k < K) ? W[(size_t)k * N + n] : 0.0f;
    float h = trunc_tf32(v);
    hiT[idx] = h;
    loT[idx] = v - h;
}

__global__ void zero_hists_kernel(unsigned* h) {
    int i = blockIdx.x * blockDim.x + threadIdx.x;
    if (i < 4 * 65536) h[i] = 0u;
}

// ---------------- tcgen05 TF32 split-GEMM, lookahead A pipeline ---------------
// C = relu(mask[m]*(A @ B^T) + bias). A raw fp32 [M, lda]; hi/lo split in regs,
// with LDG issued one iteration ahead of its STS. B^T pre-split planes.
// Tile 128x256, chunk K=32, 2-stage pipeline, 3 TF32 products (hh, hl, lh).
__global__ __launch_bounds__(256)
void gemm_tc(const float* __restrict__ A, const float* __restrict__ BhT,
             const float* __restrict__ BlT, const float* __restrict__ bias,
             const float* __restrict__ mask, float* __restrict__ C,
             float* __restrict__ part, unsigned* __restrict__ hist,
             int lda, int KP, int nchunks, int ldc) {
    extern __shared__ char smem[];
    const int tid = threadIdx.x;
    const int m0 = blockIdx.y * TILE_M;
    const int n0 = blockIdx.x * TILE_N;

#if USE_TC
    const uint32_t sb = smem_u32(smem);
    float* bias_s = reinterpret_cast<float*>(smem + SM_BIAS);
    if (tid == 0) { mbar_init(sb + 8); mbar_init(sb + 16); }
    if (tid < 32) tmem_alloc(sb, 256);
    bias_s[tid] = bias[n0 + tid];
    __syncthreads();
    uint32_t tmem;
    asm volatile("ld.shared.b32 %0, [%1];" : "=r"(tmem) : "r"(sb));

    const int Klast = lda - 4;       // last valid float4 start in raw A
    const int arow = tid >> 3;       // base row within tile; +32 per it
    const int aq = tid & 7;          // 16B quad within the 128B chunk row
    const float* Abase = A + (size_t)m0 * lda;

    // prologue: LDG chunk 0 into va
    float4 va[4];
    {
        const int kA = aq * 4;
#pragma unroll
        for (int it = 0; it < 4; it++) {
            const int row = arow + it * 32;
            va[it] = (kA <= Klast)
                ? *reinterpret_cast<const float4*>(Abase + (size_t)row * lda + kA)
                : make_float4(0.f, 0.f, 0.f, 0.f);
        }
    }

    int ph0 = 0, ph1 = 0;
#pragma unroll 1
    for (int t = 0; t < nchunks; t++) {
        const int s = t & 1;
        const int k0 = t * CHUNK;

        // issue LDG for chunk t+1 into vb (latency hidden across iteration)
        float4 vb[4];
        {
            const int tn = (t + 1 < nchunks) ? t + 1 : t;   // clamp; unused at end
            const int kA = tn * CHUNK + aq * 4;
#pragma unroll
            for (int it = 0; it < 4; it++) {
                const int row = arow + it * 32;
                vb[it] = (kA <= Klast)
                    ? *reinterpret_cast<const float4*>(Abase + (size_t)row * lda + kA)
                    : make_float4(0.f, 0.f, 0.f, 0.f);
            }
        }

        if (t >= 2) {
            if (s == 0) { mbar_wait(sb + 8, ph0);  ph0 ^= 1; }
            else        { mbar_wait(sb + 16, ph1); ph1 ^= 1; }
        }
        const uint32_t stb = sb + SM_STAGE + s * STAGE_BYTES;

        // split + STS A planes (va was loaded one iteration ago)
#pragma unroll
        for (int it = 0; it < 4; it++) {
            const int row = arow + it * 32;
            const uint32_t off = row * 128 + aq * 16;
            const uint32_t swo = off ^ ((off >> 3) & 0x70);
            float4 h, l;
            h.x = trunc_tf32(va[it].x); l.x = va[it].x - h.x;
            h.y = trunc_tf32(va[it].y); l.y = va[it].y - h.y;
            h.z = trunc_tf32(va[it].z); l.z = va[it].z - h.z;
            h.w = trunc_tf32(va[it].w); l.w = va[it].w - h.w;
            sts128(stb + swo, h);
            sts128(stb + OFF_AL + swo, l);
        }
        // B planes via cp.async: 2048 units each
#pragma unroll
        for (int it = 0; it < 8; it++) {
            const int i = tid + it * 256;
            const int row = i >> 3, q = i & 7;
            const uint32_t off = row * 128 + q * 16;
            const uint32_t swo = off ^ ((off >> 3) & 0x70);
            const size_t goff = (size_t)(n0 + row) * KP + k0 + q * 4;
            cp16(stb + OFF_BH + swo, BhT + goff);
            cp16(stb + OFF_BL + swo, BlT + goff);
        }
        cp_commit_wait0();
        asm volatile("fence.proxy.async.shared::cta;" ::: "memory");
        __syncthreads();

        if (tid == 0) {
            const uint64_t dah = mkdesc(stb);
            const uint64_t dal = mkdesc(stb + OFF_AL);
            const uint64_t dbh = mkdesc(stb + OFF_BH);
            const uint64_t dbl = mkdesc(stb + OFF_BL);
#pragma unroll
            for (int ks = 0; ks < 4; ks++) {
                const uint64_t o = ks * 2;
                mma_tf32(tmem, dah + o, dbh + o, !(t == 0 && ks == 0));
                mma_tf32(tmem, dah + o, dbl + o, true);
                mma_tf32(tmem, dal + o, dbh + o, true);
            }
            mma_commit(sb + 8 + 8 * s);
        }

        // rotate lookahead registers
#pragma unroll
        for (int it = 0; it < 4; it++) va[it] = vb[it];
    }
    // drain (in-order completion)
    {
        const int s = (nchunks - 1) & 1;
        if (s == 0) mbar_wait(sb + 8, ph0);
        else        mbar_wait(sb + 16, ph1);
    }
    asm volatile("tcgen05.fence::after_thread_sync;" ::: "memory");

    // epilogue
    const int wid = tid >> 5, lane = tid & 31;
    if (wid < 4) {
        const int m = m0 + wid * 32 + lane;
        const float msk = mask ? mask[m] : 1.0f;
        float sumsq = 0.0f;
#pragma unroll 1
        for (int cc = 0; cc < 8; cc++) {
            uint32_t r[32];
            LDTM_X32(r, tmem + cc * 32);
            asm volatile("tcgen05.wait::ld.sync.aligned;" ::: "memory");
            float vals[32];
#pragma unroll
            for (int j = 0; j < 32; j++) {
                float v = __uint_as_float(r[j]) * msk + bias_s[cc * 32 + j];
                v = fmaxf(v, 0.0f);
                sumsq += v * v;
                vals[j] = v;
            }
#pragma unroll
            for (int j4 = 0; j4 < 8; j4++) {
                float4 o4 = make_float4(vals[j4*4], vals[j4*4+1],
                                        vals[j4*4+2], vals[j4*4+3]);
                *reinterpret_cast<float4*>(C + (size_t)m * ldc + n0 + cc * 32 + j4 * 4) = o4;
            }
        }
        if (hist) {
            float nr = sqrtf(sumsq);
            part[m] = nr;                 // here part == norms
            atomicAdd(&hist[__float_as_uint(nr) >> 16], 1u);
        } else {
            part[(size_t)blockIdx.x * BATCH + m] = sumsq;
        }
    }
    __syncthreads();
    if (tid == 0) { mbar_inval(sb + 8); mbar_inval(sb + 16); }
    __syncthreads();
    if (tid < 32) tmem_dealloc(tmem, 256);

#else  // ------- generic-target fallback (correct; never selected at runtime) --
    if (tid < TILE_M) {
        const int m = m0 + tid;
        const float msk = mask ? mask[m] : 1.0f;
        float sumsq = 0.0f;
        for (int nb = 0; nb < TILE_N; nb += 32) {
            float acc[32];
#pragma unroll
            for (int j = 0; j < 32; j++) acc[j] = 0.0f;
            for (int k = 0; k < lda; k++) {
                float a = A[(size_t)m * lda + k];
                for (int j = 0; j < 32; j++)
                    acc[j] += a * (BhT[(size_t)(n0 + nb + j) * KP + k] +
                                   BlT[(size_t)(n0 + nb + j) * KP + k]);
            }
            for (int j = 0; j < 32; j++) {
                float v = fmaxf(acc[j] * msk + bias[n0 + nb + j], 0.0f);
                sumsq += v * v;
                C[(size_t)m * ldc + n0 + nb + j] = v;
            }
        }
        if (hist) {
            float nr = sqrtf(sumsq);
            part[m] = nr;
            atomicAdd(&hist[__float_as_uint(nr) >> 16], 1u);
        } else {
            part[(size_t)blockIdx.x * BATCH + m] = sumsq;
        }
    }
#endif
}

// ---------------- combine partials -> norm + hist16 ---------------------------
__global__ void combine_kernel(const float* __restrict__ part, int nb,
                               float* __restrict__ norms, unsigned* __restrict__ hist) {
    int i = blockIdx.x * blockDim.x + threadIdx.x;
    if (i >= BATCH) return;
    float s = 0.0f;
    for (int b = 0; b < nb; b++) s += part[(size_t)b * BATCH + i];
    float n = sqrtf(s);
    norms[i] = n;
    atomicAdd(&hist[__float_as_uint(n) >> 16], 1u);
}

// ---------------- select threshold: hist16 prescan + 2x 8-bit refine ----------
__global__ void select_thr_kernel(const float* __restrict__ norms,
                                  const unsigned* __restrict__ hist,
                                  float* __restrict__ thr) {
    __shared__ unsigned psum[1024];
    __shared__ unsigned h8[256];
    __shared__ unsigned s_pref, s_rank;
    const int tid = threadIdx.x;

    unsigned s = 0;
#pragma unroll 8
    for (int j = 0; j < 64; j++) s += hist[tid * 64 + j];
    psum[tid] = s;
    __syncthreads();
    if (tid == 0) {
        unsigned cum = 0;
        int slice = 0;
        for (slice = 0; slice < 1024; slice++) {
            if (cum + psum[slice] > (unsigned)R_ASC) break;
            cum += psum[slice];
        }
        unsigned b = slice * 64;
        for (;; b++) {
            if (cum + hist[b] > (unsigned)R_ASC) break;
            cum += hist[b];
        }
        s_pref = b;
        s_rank = (unsigned)R_ASC - cum;
    }
    __syncthreads();

    if (tid < 256) h8[tid] = 0u;
    __syncthreads();
    unsigned pref16 = s_pref;
    for (int i = tid; i < BATCH; i += 1024) {
        unsigned u = __float_as_uint(norms[i]);
        if ((u >> 16) == pref16) atomicAdd(&h8[(u >> 8) & 0xffu], 1u);
    }
    __syncthreads();
    if (tid == 0) {
        unsigned cum = 0, b = 0, r = s_rank;
        for (b = 0; b < 256; b++) {
            if (cum + h8[b] > r) break;
            cum += h8[b];
        }
        s_pref = (pref16 << 8) | b;
        s_rank = r - cum;
    }
    __syncthreads();

    if (tid < 256) h8[tid] = 0u;
    __syncthreads();
    unsigned pref24 = s_pref;
    for (int i = tid; i < BATCH; i += 1024) {
        unsigned u = __float_as_uint(norms[i]);
        if ((u >> 8) == pref24) atomicAdd(&h8[u & 0xffu], 1u);
    }
    __syncthreads();
    if (tid == 0) {
        unsigned cum = 0, b = 0, r = s_rank;
        for (b = 0; b < 256; b++) {
            if (cum + h8[b] > r) break;
            cum += h8[b];
        }
        thr[0] = __uint_as_float((pref24 << 8) | b);
    }
}

__global__ void write_mask_kernel(const float* __restrict__ norms,
                                  const float* __restrict__ thr,
                                  float* __restrict__ ma, float* __restrict__ mb) {
    int i = blockIdx.x * blockDim.x + threadIdx.x;
    if (i >= BATCH) return;
    float mv = (norms[i] > thr[0]) ? 1.0f : 0.0f;
    ma[i] = mv;
    mb[i] = mv;
}

// ---------------- layer 3: [B,256] -> [B,10], relu, fused norm+hist ----------
__global__ __launch_bounds__(256)
void layer3_kernel(const float* __restrict__ H2, const float* __restrict__ mask2,
                   const float* __restrict__ W3, const float* __restrict__ b3,
                   float* __restrict__ H3, float* __restrict__ norms,
                   unsigned* __restrict__ hist) {
    __shared__ float Ws[D2 * D3];
    __shared__ float bs[D3];
    for (int i = threadIdx.x; i < D2 * D3; i += blockDim.x) Ws[i] = W3[i];
    if (threadIdx.x < D3) bs[threadIdx.x] = b3[threadIdx.x];
    __syncthreads();

    int row = (blockIdx.x * blockDim.x + threadIdx.x) >> 5;
    int lane = threadIdx.x & 31;
    if (row >= BATCH) return;
    float m = mask2[row];
    float p[D3];
#pragma unroll
    for (int n = 0; n < D3; n++) p[n] = 0.0f;
#pragma unroll
    for (int t = 0; t < D2 / 32; t++) {
        int k = lane + 32 * t;
        float a = H2[(size_t)row * D2 + k] * m;
        const float* wrow = &Ws[k * D3];
#pragma unroll
        for (int n = 0; n < D3; n++) p[n] += a * wrow[n];
    }
#pragma unroll
    for (int o = 16; o; o >>= 1)
#pragma unroll
        for (int n = 0; n < D3; n++) p[n] += __shfl_down_sync(0xffffffffu, p[n], o);

    if (lane == 0) {
        float ssum = 0.0f;
#pragma unroll
        for (int n = 0; n < D3; n++) {
            float v = fmaxf(p[n] + bs[n], 0.0f);
            H3[(size_t)row * D3 + n] = v;
            ssum += v * v;
        }
        float nr = sqrtf(ssum);
        norms[row] = nr;
        atomicAdd(&hist[__float_as_uint(nr) >> 16], 1u);
    }
}

// ---------------- layer 4 + fused norm+hist ----------------------------------
__global__ __launch_bounds__(256)
void layer4_kernel(const float* __restrict__ H3, const float* __restrict__ mask3,
                   const float* __restrict__ W4, const float* __restrict__ b4,
                   float* __restrict__ H4, float* __restrict__ norms,
                   unsigned* __restrict__ hist) {
    __shared__ float Ws[D3 * D3];
    __shared__ float bs[D3];
    if (threadIdx.x < D3 * D3) Ws[threadIdx.x] = W4[threadIdx.x];
    if (threadIdx.x < D3) bs[threadIdx.x] = b4[threadIdx.x];
    __syncthreads();

    int row = blockIdx.x * blockDim.x + threadIdx.x;
    if (row >= BATCH) return;
    float m = mask3[row];
    float a[D3];
#pragma unroll
    for (int k = 0; k < D3; k++) a[k] = H3[(size_t)row * D3 + k] * m;
    float ssum = 0.0f;
#pragma unroll
    for (int n = 0; n < D3; n++) {
        float v = bs[n];
#pragma unroll
        for (int k = 0; k < D3; k++) v += a[k] * Ws[k * D3 + n];
        H4[(size_t)row * D3 + n] = v;
        ssum += v * v;
    }
    float nr = sqrtf(ssum);
    norms[row] = nr;
    atomicAdd(&hist[__float_as_uint(nr) >> 16], 1u);
}

// ---------------- softmax over masked h4 -------------------------------------
__global__ __launch_bounds__(256)
void softmax_kernel(const float* __restrict__ H4, const float* __restrict__ norms,
                    const float* __restrict__ thr, float* __restrict__ out,
                    float* __restrict__ out_mask) {
    int row = blockIdx.x * blockDim.x + threadIdx.x;
    if (row >= BATCH) return;
    float m = (norms[row] > thr[0]) ? 1.0f : 0.0f;
    out_mask[row] = m;
    float v[D3];
    float mx = -1e30f;
#pragma unroll
    for (int n = 0; n < D3; n++) {
        v[n] = H4[(size_t)row * D3 + n] * m;
        mx = fmaxf(mx, v[n]);
    }
    float s = 0.0f;
#pragma unroll
    for (int n = 0; n < D3; n++) { v[n] = expf(v[n] - mx); s += v[n]; }
    float inv = 1.0f / s;
#pragma unroll
    for (int n = 0; n < D3; n++) out[(size_t)row * D3 + n] = v[n] * inv;
}

// ---------------- launch -----------------------------------------------------
extern "C" void kernel_launch(void* const* d_in, const int* in_sizes, int n_in,
                              void* d_out, int out_size) {
    const float* x  = (const float*)d_in[0];
    const float* W1 = (const float*)d_in[1];
    const float* b1 = (const float*)d_in[2];
    const float* W2 = (const float*)d_in[3];
    const float* b2 = (const float*)d_in[4];
    const float* W3 = (const float*)d_in[5];
    const float* b3 = (const float*)d_in[6];
    const float* W4 = (const float*)d_in[7];
    const float* b4 = (const float*)d_in[8];
    float* out = (float*)d_out;

    float *h1, *h2, *h3, *h4, *nrm, *m1, *m2, *m3, *part, *thr;
    float *w1h, *w1l, *w2h, *w2l;
    unsigned* hist;
    cudaGetSymbolAddress((void**)&h1, g_h1);
    cudaGetSymbolAddress((void**)&h2, g_h2);
    cudaGetSymbolAddress((void**)&h3, g_h3);
    cudaGetSymbolAddress((void**)&h4, g_h4);
    cudaGetSymbolAddress((void**)&nrm, g_norm);
    cudaGetSymbolAddress((void**)&m1, g_mask1);
    cudaGetSymbolAddress((void**)&m2, g_mask2);
    cudaGetSymbolAddress((void**)&m3, g_mask3);
    cudaGetSymbolAddress((void**)&part, g_part);
    cudaGetSymbolAddress((void**)&thr, g_thr);
    cudaGetSymbolAddress((void**)&w1h, g_w1hT);
    cudaGetSymbolAddress((void**)&w1l, g_w1lT);
    cudaGetSymbolAddress((void**)&w2h, g_w2hT);
    cudaGetSymbolAddress((void**)&w2l, g_w2lT);
    cudaGetSymbolAddress((void**)&hist, g_hist);

    cudaFuncSetAttribute(gemm_tc, cudaFuncAttributeMaxDynamicSharedMemorySize, GEMM_SMEM);

    float* out_m1 = out + (size_t)BATCH * D3;
    float* out_m2 = out_m1 + BATCH;
    float* out_m3 = out_m2 + BATCH;
    float* out_m4 = out_m3 + BATCH;

    unsigned* hist0 = hist;
    unsigned* hist1 = hist + 65536;
    unsigned* hist2 = hist + 2 * 65536;
    unsigned* hist3 = hist + 3 * 65536;

    zero_hists_kernel<<<(4 * 65536) / 256, 256>>>(hist);
    prep_split_T<<<(D1 * KP1 + 255) / 256, 256>>>(W1, w1h, w1l, D0, D1, KP1);
    prep_split_T<<<(D2 * KP2 + 255) / 256, 256>>>(W2, w2h, w2l, D1, D2, KP2);

    // Layer 1: [B,784] -> [B,512]
    {
        dim3 grid(D1 / TILE_N, BATCH / TILE_M);   // (2, 512)
        gemm_tc<<<grid, 256, GEMM_SMEM>>>(x, w1h, w1l, b1, nullptr,
                                          h1, part, nullptr,
                                          D0, KP1, KP1 / CHUNK, D1);
    }
    combine_kernel<<<BATCH / 256, 256>>>(part, 2, nrm, hist0);
    select_thr_kernel<<<1, 1024>>>(nrm, hist0, thr);
    write_mask_kernel<<<BATCH / 256, 256>>>(nrm, thr, m1, out_m1);

    // Layer 2: [B,512] -> [B,256], mask in epilogue, fused norm+hist
    {
        dim3 grid(D2 / TILE_N, BATCH / TILE_M);   // (1, 512)
        gemm_tc<<<grid, 256, GEMM_SMEM>>>(h1, w2h, w2l, b2, m1,
                                          h2, nrm, hist1,
                                          D1, KP2, KP2 / CHUNK, D2);
    }
    select_thr_kernel<<<1, 1024>>>(nrm, hist1, thr);
    write_mask_kernel<<<BATCH / 256, 256>>>(nrm, thr, m2, out_m2);

    // Layer 3
    layer3_kernel<<<(BATCH * 32) / 256, 256>>>(h2, m2, W3, b3, h3, nrm, hist2);
    select_thr_kernel<<<1, 1024>>>(nrm, hist2, thr);
    write_mask_kernel<<<BATCH / 256, 256>>>(nrm, thr, m3, out_m3);

    // Layer 4
    layer4_kernel<<<BATCH / 256, 256>>>(h3, m3, W4, b4, h4, nrm, hist3);
    select_thr_kernel<<<1, 1024>>>(nrm, hist3, thr);

    // Softmax + mask4 write
    softmax_kernel<<<BATCH / 256, 256>>>(h4, nrm, thr, out, out_m4);
}